// round 5
// baseline (speedup 1.0000x reference)
#include <cuda_runtime.h>
#include <cstdint>

#define SCALE_Q 0.17677669529663687f   // 32^-0.5

// scratch (static device globals; no runtime allocation)
__device__ float g_qkv[262144UL * 768]; // [m][768]: q | k | v
__device__ float g_ao [262144UL * 256]; // [m][256]: attention output

__device__ __forceinline__ uint32_t f2tf(float x) {
    uint32_t r;
    asm("cvt.rna.tf32.f32 %0, %1;" : "=r"(r) : "f"(x));
    return r;
}

__device__ __forceinline__ void mma_tf32(float c[4], uint32_t a0, uint32_t a1,
                                         uint32_t a2, uint32_t a3,
                                         uint32_t b0, uint32_t b1) {
    asm volatile(
        "mma.sync.aligned.m16n8k8.row.col.f32.tf32.tf32.f32 "
        "{%0,%1,%2,%3},{%4,%5,%6,%7},{%8,%9},{%0,%1,%2,%3};\n"
        : "+f"(c[0]), "+f"(c[1]), "+f"(c[2]), "+f"(c[3])
        : "r"(a0), "r"(a1), "r"(a2), "r"(a3), "r"(b0), "r"(b1));
}

#define AS_STRIDE 260                   // % 32 == 4 -> conflict-free LDS.128
#define BS_STRIDE 36
#define BS_SIZE   (256 * BS_STRIDE)     // one stage: 256 N-rows x 32 k
#define GEMM_SMEM ((128 * AS_STRIDE + 2 * BS_SIZE) * 4)   // ~202 KB

// ---------------------------------------------------------------------------
// tf32 GEMM, A-tile (128x256) resident in smem for ALL N-chunks.
// N looped in chunks of 256. 512 threads = 16 warps, 4m x 4n,
// warp tile 32(M) x 64(N): 0.375 LDS.128 per MMA.
// ---------------------------------------------------------------------------
template <int MODE>
__global__ __launch_bounds__(512, 1) void gemm_tf32(
    const float* __restrict__ A,
    const float* __restrict__ W,      // [N][256] row-major
    const float* __restrict__ bias,
    float* __restrict__ Cout)
{
    constexpr int NCH = (MODE == 0) ? 3 : 1;     // chunks of 256 N
    constexpr int T   = NCH * 8;

    extern __shared__ uint32_t sh[];
    uint32_t* As = sh;                          // 128 x AS_STRIDE
    uint32_t* Bs = sh + 128 * AS_STRIDE;        // 2 x BS_SIZE (double buffer)
    __shared__ const float* arow[128];
    __shared__ float*       crow[128];

    const int tid = threadIdx.x;
    const int m0  = blockIdx.x * 128;

    if (tid < 128) {
        const int m = m0 + tid;
        if (MODE == 0) {
            const int b  = m >> 16;
            const int wi = (m >> 6) & 1023;
            const int p  = m & 63;
            const int wh = wi >> 5, wc = wi & 31;
            const int pi = p >> 3,  pj = p & 7;
            const int h  = ((wh << 3) + pi + 4) & 255;   // roll(-4)
            const int w  = ((wc << 3) + pj + 4) & 255;
            arow[tid] = A + (size_t)((b << 16) | (h << 8) | w) * 256;
            crow[tid] = g_qkv + (size_t)m * 768;
        } else {
            const int bp = m >> 16;
            const int h  = (m >> 8) & 255;
            const int w  = m & 255;
            const int wh  = h >> 3, pi = h & 7;
            const int wcq = w >> 3, pj = w & 7;
            const int n   = (bp << 8) | (wh << 3) | (wcq >> 2);  // unscramble
            const int bb  = wcq & 3;
            const int p   = (pi << 3) | pj;
            arow[tid] = g_ao + ((size_t)((bb << 16) | (n << 6) | p)) * 256;
            const int fh = (h + 4) & 255, fw = (w + 4) & 255;    // roll(+4)
            crow[tid] = Cout + (size_t)((bp << 16) | (fh << 8) | fw) * 256;
        }
    }
    __syncthreads();

    // ---- A tile (128 x 256) -> smem, packed, loaded ONCE ----
#pragma unroll
    for (int i = 0; i < 16; i++) {
        const int idx = tid + i * 512;
        const int r = idx >> 6, k4 = (idx & 63) << 2;
        const float4 v = *(const float4*)(arow[r] + k4);
        uint32_t* d = As + r * AS_STRIDE + (k4 & ~31) + ((k4 >> 2) & 7);
        d[0]  = f2tf(v.x); d[8]  = f2tf(v.y);
        d[16] = f2tf(v.z); d[24] = f2tf(v.w);
    }

    // B staging: thread loads rows bn, bn+64, bn+128, bn+192; 4 k-floats each
    const int bn = tid >> 3, bj = tid & 7;
#pragma unroll
    for (int r = 0; r < 4; r++) {
        const float4 v = *(const float4*)(W + (size_t)(bn + r * 64) * 256 + bj * 4);
        uint32_t* d = Bs + (bn + r * 64) * BS_STRIDE + bj;
        d[0] = f2tf(v.x); d[8] = f2tf(v.y); d[16] = f2tf(v.z); d[24] = f2tf(v.w);
    }

    const int warp = tid >> 5, lane = tid & 31;
    const int wm = warp >> 2, wn = warp & 3;     // 4m x 4n
    const int g = lane >> 2, tg = lane & 3;

    float c[2][8][4];
#pragma unroll
    for (int mt = 0; mt < 2; mt++)
#pragma unroll
        for (int nt = 0; nt < 8; nt++)
#pragma unroll
            for (int i = 0; i < 4; i++) c[mt][nt][i] = 0.f;

    float4 pv[4];
    for (int it = 0; it < T; it++) {
        if (it + 1 < T) {   // issue next-stage global loads early
            const int nc = (it + 1) >> 3, kc = (it + 1) & 7;
            const float* wb = W + (size_t)(nc * 256 + bn) * 256 + kc * 32 + bj * 4;
#pragma unroll
            for (int r = 0; r < 4; r++)
                pv[r] = *(const float4*)(wb + (size_t)r * 64 * 256);
        }
        __syncthreads();    // current B buffer ready

        const int kc = it & 7;
        const uint32_t* abase = As + kc * 32 + tg * 8;
        const uint32_t* bbase = Bs + (it & 1) * BS_SIZE + tg * 8;

        uint32_t av[2][2][8];
#pragma unroll
        for (int mt = 0; mt < 2; mt++)
#pragma unroll
            for (int h2 = 0; h2 < 2; h2++) {
                const uint32_t* p = abase + (wm * 32 + mt * 16 + h2 * 8 + g) * AS_STRIDE;
                *(uint4*)&av[mt][h2][0] = *(const uint4*)p;
                *(uint4*)&av[mt][h2][4] = *(const uint4*)(p + 4);
            }
#pragma unroll
        for (int nt = 0; nt < 8; nt++) {
            uint32_t bv[8];
            const uint32_t* p = bbase + (wn * 64 + nt * 8 + g) * BS_STRIDE;
            *(uint4*)&bv[0] = *(const uint4*)p;
            *(uint4*)&bv[4] = *(const uint4*)(p + 4);
#pragma unroll
            for (int j = 0; j < 4; j++)
#pragma unroll
                for (int mt = 0; mt < 2; mt++)
                    mma_tf32(c[mt][nt],
                             av[mt][0][2*j], av[mt][1][2*j],
                             av[mt][0][2*j+1], av[mt][1][2*j+1],
                             bv[2*j], bv[2*j+1]);
        }

        if (it + 1 < T) {   // store next stage into other buffer
            uint32_t* d = Bs + ((it + 1) & 1) * BS_SIZE + bn * BS_STRIDE + bj;
#pragma unroll
            for (int r = 0; r < 4; r++) {
                uint32_t* dr = d + r * 64 * BS_STRIDE;
                dr[0] = f2tf(pv[r].x); dr[8]  = f2tf(pv[r].y);
                dr[16] = f2tf(pv[r].z); dr[24] = f2tf(pv[r].w);
            }
        }

        if (kc == 7) {      // epilogue for this 256-wide N chunk
            const int nc = it >> 3;
#pragma unroll
            for (int mt = 0; mt < 2; mt++)
#pragma unroll
                for (int nt = 0; nt < 8; nt++) {
                    const int col = nc * 256 + wn * 64 + nt * 8 + tg * 2;
                    const float b0 = bias[col], b1 = bias[col + 1];
#pragma unroll
                    for (int h2 = 0; h2 < 2; h2++) {
                        const int r = wm * 32 + mt * 16 + h2 * 8 + g;
                        float v0 = c[mt][nt][h2 * 2]     + b0;
                        float v1 = c[mt][nt][h2 * 2 + 1] + b1;
                        if (MODE == 0 && col < 256) { v0 *= SCALE_Q; v1 *= SCALE_Q; }
                        crow[r][col]     = v0;
                        crow[r][col + 1] = v1;
                        c[mt][nt][h2 * 2]     = 0.f;
                        c[mt][nt][h2 * 2 + 1] = 0.f;
                    }
                }
        }
    }
}

// ---------------------------------------------------------------------------
// Tensor-core attention (unchanged from round 4).
// ---------------------------------------------------------------------------
__global__ __launch_bounds__(128) void attn_kernel(const float* __restrict__ rel_pos)
{
    __shared__ uint32_t qkp[4608];   // Q[64][36] @0, K[64][36] @2304 ; P[64][72] alias
    __shared__ uint32_t vsm[32 * 68];// V^T packed [dim 32][tok 64 packed]
    __shared__ float relb[228];

    const int tid = threadIdx.x;
    const int win = blockIdx.x;
    const int hh  = blockIdx.y;
    const int wloc = win & 1023;
    const bool maskH = ((wloc >> 5) == 31);
    const bool maskW = ((wloc & 31) == 31);

    const float* base = g_qkv + (size_t)win * 49152 + hh * 32;
#pragma unroll
    for (int i = 0; i < 4; i++) {
        const int idx = tid + i * 128;
        const int t = idx >> 3, j8 = idx & 7;
        const float* src = base + (size_t)t * 768 + j8 * 4;
        const float4 q4 = *(const float4*)(src);
        const float4 k4 = *(const float4*)(src + 256);
        const float4 v4 = *(const float4*)(src + 512);
        uint32_t* qd = qkp + t * 36 + j8;
        qd[0] = f2tf(q4.x); qd[8] = f2tf(q4.y); qd[16] = f2tf(q4.z); qd[24] = f2tf(q4.w);
        uint32_t* kd = qkp + 2304 + t * 36 + j8;
        kd[0] = f2tf(k4.x); kd[8] = f2tf(k4.y); kd[16] = f2tf(k4.z); kd[24] = f2tf(k4.w);
        const int tp = (t & 32) + ((t & 3) << 3) + ((t >> 2) & 7);
        uint32_t* vd = vsm + (size_t)(j8 * 4) * 68 + tp;
        vd[0] = f2tf(v4.x); vd[68] = f2tf(v4.y); vd[136] = f2tf(v4.z); vd[204] = f2tf(v4.w);
    }
    for (int i = tid; i < 225; i += 128) relb[i] = rel_pos[hh * 225 + i];
    __syncthreads();

    const int w = tid >> 5, lane = tid & 31;
    const int g = lane >> 2, tg = lane & 3;

    uint32_t af[2][8];
#pragma unroll
    for (int h2 = 0; h2 < 2; h2++) {
        const uint32_t* p = qkp + (w * 16 + h2 * 8 + g) * 36 + tg * 8;
        *(uint4*)&af[h2][0] = *(const uint4*)p;
        *(uint4*)&af[h2][4] = *(const uint4*)(p + 4);
    }
    float c[8][4];
#pragma unroll
    for (int nt = 0; nt < 8; nt++)
#pragma unroll
        for (int i = 0; i < 4; i++) c[nt][i] = 0.f;

#pragma unroll
    for (int nt = 0; nt < 8; nt++) {
        uint32_t bf[8];
        const uint32_t* p = qkp + 2304 + (nt * 8 + g) * 36 + tg * 8;
        *(uint4*)&bf[0] = *(const uint4*)p;
        *(uint4*)&bf[4] = *(const uint4*)(p + 4);
#pragma unroll
        for (int j = 0; j < 4; j++)
            mma_tf32(c[nt], af[0][2*j], af[1][2*j], af[0][2*j+1], af[1][2*j+1],
                     bf[2*j], bf[2*j+1]);
    }

    const int r0 = w * 16 + g, r1 = r0 + 8;
    const int pi0 = r0 >> 3, pj0 = r0 & 7;
    const int pi1 = r1 >> 3, pj1 = r1 & 7;
#pragma unroll
    for (int nt = 0; nt < 8; nt++) {
#pragma unroll
        for (int b = 0; b < 2; b++) {
            const int q = nt * 8 + tg * 2 + b;
            const int qi = q >> 3, qj = q & 7;
            const bool m0 = (maskH && ((pi0 < 4) != (qi < 4))) ||
                            (maskW && ((pj0 < 4) != (qj < 4)));
            const bool m1 = (maskH && ((pi1 < 4) != (qi < 4))) ||
                            (maskW && ((pj1 < 4) != (qj < 4)));
            c[nt][b]     = m0 ? -1e30f : c[nt][b]     + relb[(pi0 - qi + 7) * 15 + (pj0 - qj + 7)];
            c[nt][2 + b] = m1 ? -1e30f : c[nt][2 + b] + relb[(pi1 - qi + 7) * 15 + (pj1 - qj + 7)];
        }
    }

    float m0 = -1e30f, m1 = -1e30f;
#pragma unroll
    for (int nt = 0; nt < 8; nt++) {
        m0 = fmaxf(m0, fmaxf(c[nt][0], c[nt][1]));
        m1 = fmaxf(m1, fmaxf(c[nt][2], c[nt][3]));
    }
    m0 = fmaxf(m0, __shfl_xor_sync(0xffffffffu, m0, 1));
    m0 = fmaxf(m0, __shfl_xor_sync(0xffffffffu, m0, 2));
    m1 = fmaxf(m1, __shfl_xor_sync(0xffffffffu, m1, 1));
    m1 = fmaxf(m1, __shfl_xor_sync(0xffffffffu, m1, 2));
    float s0 = 0.f, s1 = 0.f;
#pragma unroll
    for (int nt = 0; nt < 8; nt++) {
        c[nt][0] = __expf(c[nt][0] - m0); s0 += c[nt][0];
        c[nt][1] = __expf(c[nt][1] - m0); s0 += c[nt][1];
        c[nt][2] = __expf(c[nt][2] - m1); s1 += c[nt][2];
        c[nt][3] = __expf(c[nt][3] - m1); s1 += c[nt][3];
    }
    s0 += __shfl_xor_sync(0xffffffffu, s0, 1);
    s0 += __shfl_xor_sync(0xffffffffu, s0, 2);
    s1 += __shfl_xor_sync(0xffffffffu, s1, 1);
    s1 += __shfl_xor_sync(0xffffffffu, s1, 2);
    const float inv0 = 1.f / s0, inv1 = 1.f / s1;

    __syncthreads();

#pragma unroll
    for (int nt = 0; nt < 8; nt++)
#pragma unroll
        for (int b = 0; b < 2; b++) {
            const int q = nt * 8 + tg * 2 + b;
            const int pos = (q & 32) + ((q & 3) << 3) + ((q >> 2) & 7);
            qkp[r0 * 72 + pos] = f2tf(c[nt][b]     * inv0);
            qkp[r1 * 72 + pos] = f2tf(c[nt][2 + b] * inv1);
        }
    __syncthreads();

    uint32_t ap[2][2][8];
#pragma unroll
    for (int h2 = 0; h2 < 2; h2++)
#pragma unroll
        for (int ch = 0; ch < 2; ch++) {
            const uint32_t* p = qkp + (w * 16 + h2 * 8 + g) * 72 + ch * 32 + tg * 8;
            *(uint4*)&ap[h2][ch][0] = *(const uint4*)p;
            *(uint4*)&ap[h2][ch][4] = *(const uint4*)(p + 4);
        }
    float o[4][4];
#pragma unroll
    for (int nt = 0; nt < 4; nt++)
#pragma unroll
        for (int i = 0; i < 4; i++) o[nt][i] = 0.f;

#pragma unroll
    for (int nt = 0; nt < 4; nt++) {
        uint32_t bf0[8], bf1[8];
        const uint32_t* p = vsm + (nt * 8 + g) * 68 + tg * 8;
        *(uint4*)&bf0[0] = *(const uint4*)p;
        *(uint4*)&bf0[4] = *(const uint4*)(p + 4);
        *(uint4*)&bf1[0] = *(const uint4*)(p + 32);
        *(uint4*)&bf1[4] = *(const uint4*)(p + 36);
#pragma unroll
        for (int j = 0; j < 4; j++)
            mma_tf32(o[nt], ap[0][0][2*j], ap[1][0][2*j], ap[0][0][2*j+1], ap[1][0][2*j+1],
                     bf0[2*j], bf0[2*j+1]);
#pragma unroll
        for (int j = 0; j < 4; j++)
            mma_tf32(o[nt], ap[0][1][2*j], ap[1][1][2*j], ap[0][1][2*j+1], ap[1][1][2*j+1],
                     bf1[2*j], bf1[2*j+1]);
    }

    float* ob = g_ao + (size_t)win * 16384 + hh * 32;
#pragma unroll
    for (int nt = 0; nt < 4; nt++) {
        const int d = nt * 8 + tg * 2;
        *(float2*)&ob[(size_t)r0 * 256 + d] = make_float2(o[nt][0], o[nt][1]);
        *(float2*)&ob[(size_t)r1 * 256 + d] = make_float2(o[nt][2], o[nt][3]);
    }
}

// ---------------------------------------------------------------------------
extern "C" void kernel_launch(void* const* d_in, const int* in_sizes, int n_in,
                              void* d_out, int out_size)
{
    const float* x       = (const float*)d_in[0];
    const float* w_qkv   = (const float*)d_in[1];
    const float* b_qkv   = (const float*)d_in[2];
    const float* rel_pos = (const float*)d_in[3];
    const float* w_out   = (const float*)d_in[4];
    const float* b_out   = (const float*)d_in[5];
    float* out = (float*)d_out;

    cudaFuncSetAttribute((const void*)gemm_tf32<0>,
                         cudaFuncAttributeMaxDynamicSharedMemorySize, GEMM_SMEM);
    cudaFuncSetAttribute((const void*)gemm_tf32<1>,
                         cudaFuncAttributeMaxDynamicSharedMemorySize, GEMM_SMEM);

    gemm_tf32<0><<<2048, 512, GEMM_SMEM>>>(x, w_qkv, b_qkv, nullptr);
    attn_kernel<<<dim3(4096, 8), 128>>>(rel_pos);
    gemm_tf32<1><<<2048, 512, GEMM_SMEM>>>(nullptr, w_out, b_out, out);
}

// round 6
// speedup vs baseline: 1.0643x; 1.0643x over previous
#include <cuda_runtime.h>
#include <cstdint>

#define SCALE_Q 0.17677669529663687f   // 32^-0.5

// scratch (static device globals; no runtime allocation)
__device__ float g_qkv[262144UL * 768]; // [m][768]: q | k | v
__device__ float g_ao [262144UL * 256]; // [m][256]: attention output

__device__ __forceinline__ uint32_t f2tf(float x) {
    uint32_t r;
    asm("cvt.rna.tf32.f32 %0, %1;" : "=r"(r) : "f"(x));
    return r;
}

__device__ __forceinline__ void mma_tf32(float c[4], uint32_t a0, uint32_t a1,
                                         uint32_t a2, uint32_t a3,
                                         uint32_t b0, uint32_t b1) {
    asm volatile(
        "mma.sync.aligned.m16n8k8.row.col.f32.tf32.tf32.f32 "
        "{%0,%1,%2,%3},{%4,%5,%6,%7},{%8,%9},{%0,%1,%2,%3};\n"
        : "+f"(c[0]), "+f"(c[1]), "+f"(c[2]), "+f"(c[3])
        : "r"(a0), "r"(a1), "r"(a2), "r"(a3), "r"(b0), "r"(b1));
}

#define AS_STRIDE 260                   // % 32 == 4 -> conflict-free LDS.128
#define BS_STRIDE 36
#define BS_SIZE   (128 * BS_STRIDE)     // one stage: 128 N-rows x 32 k
#define GEMM_SMEM ((64 * AS_STRIDE + 2 * BS_SIZE) * 4)   // ~103 KB -> 2 CTAs/SM

// ---------------------------------------------------------------------------
// tf32 GEMM: block tile 64(M) x 128(N-chunk), A-tile resident for all chunks.
// 256 threads = 8 warps (2m x 4n), warp tile 32x32 (96-reg sweet spot).
// Two CTAs co-resident per SM -> barriers overlap across CTAs.
// ---------------------------------------------------------------------------
template <int MODE>
__global__ __launch_bounds__(256, 2) void gemm_tf32(
    const float* __restrict__ A,
    const float* __restrict__ W,      // [N][256] row-major
    const float* __restrict__ bias,
    float* __restrict__ Cout)
{
    constexpr int NCH = (MODE == 0) ? 6 : 2;     // chunks of 128 N
    constexpr int T   = NCH * 8;

    extern __shared__ uint32_t sh[];
    uint32_t* As = sh;                          // 64 x AS_STRIDE
    uint32_t* Bs = sh + 64 * AS_STRIDE;         // 2 x BS_SIZE (double buffer)
    __shared__ const float* arow[64];
    __shared__ float*       crow[64];

    const int tid = threadIdx.x;
    const int m0  = blockIdx.x * 64;

    if (tid < 64) {
        const int m = m0 + tid;
        if (MODE == 0) {
            const int b  = m >> 16;
            const int wi = (m >> 6) & 1023;
            const int p  = m & 63;
            const int wh = wi >> 5, wc = wi & 31;
            const int pi = p >> 3,  pj = p & 7;
            const int h  = ((wh << 3) + pi + 4) & 255;   // roll(-4)
            const int w  = ((wc << 3) + pj + 4) & 255;
            arow[tid] = A + (size_t)((b << 16) | (h << 8) | w) * 256;
            crow[tid] = g_qkv + (size_t)m * 768;
        } else {
            const int bp = m >> 16;
            const int h  = (m >> 8) & 255;
            const int w  = m & 255;
            const int wh  = h >> 3, pi = h & 7;
            const int wcq = w >> 3, pj = w & 7;
            const int n   = (bp << 8) | (wh << 3) | (wcq >> 2);  // unscramble
            const int bb  = wcq & 3;
            const int p   = (pi << 3) | pj;
            arow[tid] = g_ao + ((size_t)((bb << 16) | (n << 6) | p)) * 256;
            const int fh = (h + 4) & 255, fw = (w + 4) & 255;    // roll(+4)
            crow[tid] = Cout + (size_t)((bp << 16) | (fh << 8) | fw) * 256;
        }
    }
    __syncthreads();

    // ---- A tile (64 x 256) -> smem, packed, loaded ONCE ----
#pragma unroll
    for (int i = 0; i < 16; i++) {
        const int idx = tid + i * 256;
        const int r = idx >> 6, k4 = (idx & 63) << 2;
        const float4 v = *(const float4*)(arow[r] + k4);
        uint32_t* d = As + r * AS_STRIDE + (k4 & ~31) + ((k4 >> 2) & 7);
        d[0]  = f2tf(v.x); d[8]  = f2tf(v.y);
        d[16] = f2tf(v.z); d[24] = f2tf(v.w);
    }

    // B staging: thread covers rows bn, bn+32, bn+64, bn+96; 4 k-floats each
    const int bn = tid >> 3, bj = tid & 7;
#pragma unroll
    for (int r = 0; r < 4; r++) {
        const float4 v = *(const float4*)(W + (size_t)(bn + r * 32) * 256 + bj * 4);
        uint32_t* d = Bs + (bn + r * 32) * BS_STRIDE + bj;
        d[0] = f2tf(v.x); d[8] = f2tf(v.y); d[16] = f2tf(v.z); d[24] = f2tf(v.w);
    }

    const int warp = tid >> 5, lane = tid & 31;
    const int wm = warp >> 2, wn = warp & 3;     // 2m x 4n
    const int g = lane >> 2, tg = lane & 3;

    float c[2][4][4];
#pragma unroll
    for (int mt = 0; mt < 2; mt++)
#pragma unroll
        for (int nt = 0; nt < 4; nt++)
#pragma unroll
            for (int i = 0; i < 4; i++) c[mt][nt][i] = 0.f;

    float4 pv[4];
    for (int it = 0; it < T; it++) {
        if (it + 1 < T) {   // issue next-stage global loads early
            const int nc = (it + 1) >> 3, kc = (it + 1) & 7;
            const float* wb = W + (size_t)(nc * 128 + bn) * 256 + kc * 32 + bj * 4;
#pragma unroll
            for (int r = 0; r < 4; r++)
                pv[r] = *(const float4*)(wb + (size_t)r * 32 * 256);
        }
        __syncthreads();    // current B buffer ready

        const int kc = it & 7;
        const uint32_t* abase = As + kc * 32 + tg * 8;
        const uint32_t* bbase = Bs + (it & 1) * BS_SIZE + tg * 8;

        uint32_t av[2][2][8];
#pragma unroll
        for (int mt = 0; mt < 2; mt++)
#pragma unroll
            for (int h2 = 0; h2 < 2; h2++) {
                const uint32_t* p = abase + (wm * 32 + mt * 16 + h2 * 8 + g) * AS_STRIDE;
                *(uint4*)&av[mt][h2][0] = *(const uint4*)p;
                *(uint4*)&av[mt][h2][4] = *(const uint4*)(p + 4);
            }
#pragma unroll
        for (int nt = 0; nt < 4; nt++) {
            uint32_t bv[8];
            const uint32_t* p = bbase + (wn * 32 + nt * 8 + g) * BS_STRIDE;
            *(uint4*)&bv[0] = *(const uint4*)p;
            *(uint4*)&bv[4] = *(const uint4*)(p + 4);
#pragma unroll
            for (int j = 0; j < 4; j++)
#pragma unroll
                for (int mt = 0; mt < 2; mt++)
                    mma_tf32(c[mt][nt],
                             av[mt][0][2*j], av[mt][1][2*j],
                             av[mt][0][2*j+1], av[mt][1][2*j+1],
                             bv[2*j], bv[2*j+1]);
        }

        if (it + 1 < T) {   // store next stage into other buffer
            uint32_t* d = Bs + ((it + 1) & 1) * BS_SIZE + bn * BS_STRIDE + bj;
#pragma unroll
            for (int r = 0; r < 4; r++) {
                uint32_t* dr = d + r * 32 * BS_STRIDE;
                dr[0] = f2tf(pv[r].x); dr[8]  = f2tf(pv[r].y);
                dr[16] = f2tf(pv[r].z); dr[24] = f2tf(pv[r].w);
            }
        }

        if (kc == 7) {      // epilogue for this 128-wide N chunk
            const int nc = it >> 3;
#pragma unroll
            for (int mt = 0; mt < 2; mt++)
#pragma unroll
                for (int nt = 0; nt < 4; nt++) {
                    const int col = nc * 128 + wn * 32 + nt * 8 + tg * 2;
                    const float b0 = bias[col], b1 = bias[col + 1];
#pragma unroll
                    for (int h2 = 0; h2 < 2; h2++) {
                        const int r = wm * 32 + mt * 16 + h2 * 8 + g;
                        float v0 = c[mt][nt][h2 * 2]     + b0;
                        float v1 = c[mt][nt][h2 * 2 + 1] + b1;
                        if (MODE == 0 && col < 256) { v0 *= SCALE_Q; v1 *= SCALE_Q; }
                        crow[r][col]     = v0;
                        crow[r][col + 1] = v1;
                        c[mt][nt][h2 * 2]     = 0.f;
                        c[mt][nt][h2 * 2 + 1] = 0.f;
                    }
                }
        }
    }
}

// ---------------------------------------------------------------------------
// Tensor-core attention (unchanged).
// ---------------------------------------------------------------------------
__global__ __launch_bounds__(128) void attn_kernel(const float* __restrict__ rel_pos)
{
    __shared__ uint32_t qkp[4608];   // Q[64][36] @0, K[64][36] @2304 ; P[64][72] alias
    __shared__ uint32_t vsm[32 * 68];// V^T packed [dim 32][tok 64 packed]
    __shared__ float relb[228];

    const int tid = threadIdx.x;
    const int win = blockIdx.x;
    const int hh  = blockIdx.y;
    const int wloc = win & 1023;
    const bool maskH = ((wloc >> 5) == 31);
    const bool maskW = ((wloc & 31) == 31);

    const float* base = g_qkv + (size_t)win * 49152 + hh * 32;
#pragma unroll
    for (int i = 0; i < 4; i++) {
        const int idx = tid + i * 128;
        const int t = idx >> 3, j8 = idx & 7;
        const float* src = base + (size_t)t * 768 + j8 * 4;
        const float4 q4 = *(const float4*)(src);
        const float4 k4 = *(const float4*)(src + 256);
        const float4 v4 = *(const float4*)(src + 512);
        uint32_t* qd = qkp + t * 36 + j8;
        qd[0] = f2tf(q4.x); qd[8] = f2tf(q4.y); qd[16] = f2tf(q4.z); qd[24] = f2tf(q4.w);
        uint32_t* kd = qkp + 2304 + t * 36 + j8;
        kd[0] = f2tf(k4.x); kd[8] = f2tf(k4.y); kd[16] = f2tf(k4.z); kd[24] = f2tf(k4.w);
        const int tp = (t & 32) + ((t & 3) << 3) + ((t >> 2) & 7);
        uint32_t* vd = vsm + (size_t)(j8 * 4) * 68 + tp;
        vd[0] = f2tf(v4.x); vd[68] = f2tf(v4.y); vd[136] = f2tf(v4.z); vd[204] = f2tf(v4.w);
    }
    for (int i = tid; i < 225; i += 128) relb[i] = rel_pos[hh * 225 + i];
    __syncthreads();

    const int w = tid >> 5, lane = tid & 31;
    const int g = lane >> 2, tg = lane & 3;

    uint32_t af[2][8];
#pragma unroll
    for (int h2 = 0; h2 < 2; h2++) {
        const uint32_t* p = qkp + (w * 16 + h2 * 8 + g) * 36 + tg * 8;
        *(uint4*)&af[h2][0] = *(const uint4*)p;
        *(uint4*)&af[h2][4] = *(const uint4*)(p + 4);
    }
    float c[8][4];
#pragma unroll
    for (int nt = 0; nt < 8; nt++)
#pragma unroll
        for (int i = 0; i < 4; i++) c[nt][i] = 0.f;

#pragma unroll
    for (int nt = 0; nt < 8; nt++) {
        uint32_t bf[8];
        const uint32_t* p = qkp + 2304 + (nt * 8 + g) * 36 + tg * 8;
        *(uint4*)&bf[0] = *(const uint4*)p;
        *(uint4*)&bf[4] = *(const uint4*)(p + 4);
#pragma unroll
        for (int j = 0; j < 4; j++)
            mma_tf32(c[nt], af[0][2*j], af[1][2*j], af[0][2*j+1], af[1][2*j+1],
                     bf[2*j], bf[2*j+1]);
    }

    const int r0 = w * 16 + g, r1 = r0 + 8;
    const int pi0 = r0 >> 3, pj0 = r0 & 7;
    const int pi1 = r1 >> 3, pj1 = r1 & 7;
#pragma unroll
    for (int nt = 0; nt < 8; nt++) {
#pragma unroll
        for (int b = 0; b < 2; b++) {
            const int q = nt * 8 + tg * 2 + b;
            const int qi = q >> 3, qj = q & 7;
            const bool m0 = (maskH && ((pi0 < 4) != (qi < 4))) ||
                            (maskW && ((pj0 < 4) != (qj < 4)));
            const bool m1 = (maskH && ((pi1 < 4) != (qi < 4))) ||
                            (maskW && ((pj1 < 4) != (qj < 4)));
            c[nt][b]     = m0 ? -1e30f : c[nt][b]     + relb[(pi0 - qi + 7) * 15 + (pj0 - qj + 7)];
            c[nt][2 + b] = m1 ? -1e30f : c[nt][2 + b] + relb[(pi1 - qi + 7) * 15 + (pj1 - qj + 7)];
        }
    }

    float m0 = -1e30f, m1 = -1e30f;
#pragma unroll
    for (int nt = 0; nt < 8; nt++) {
        m0 = fmaxf(m0, fmaxf(c[nt][0], c[nt][1]));
        m1 = fmaxf(m1, fmaxf(c[nt][2], c[nt][3]));
    }
    m0 = fmaxf(m0, __shfl_xor_sync(0xffffffffu, m0, 1));
    m0 = fmaxf(m0, __shfl_xor_sync(0xffffffffu, m0, 2));
    m1 = fmaxf(m1, __shfl_xor_sync(0xffffffffu, m1, 1));
    m1 = fmaxf(m1, __shfl_xor_sync(0xffffffffu, m1, 2));
    float s0 = 0.f, s1 = 0.f;
#pragma unroll
    for (int nt = 0; nt < 8; nt++) {
        c[nt][0] = __expf(c[nt][0] - m0); s0 += c[nt][0];
        c[nt][1] = __expf(c[nt][1] - m0); s0 += c[nt][1];
        c[nt][2] = __expf(c[nt][2] - m1); s1 += c[nt][2];
        c[nt][3] = __expf(c[nt][3] - m1); s1 += c[nt][3];
    }
    s0 += __shfl_xor_sync(0xffffffffu, s0, 1);
    s0 += __shfl_xor_sync(0xffffffffu, s0, 2);
    s1 += __shfl_xor_sync(0xffffffffu, s1, 1);
    s1 += __shfl_xor_sync(0xffffffffu, s1, 2);
    const float inv0 = 1.f / s0, inv1 = 1.f / s1;

    __syncthreads();

#pragma unroll
    for (int nt = 0; nt < 8; nt++)
#pragma unroll
        for (int b = 0; b < 2; b++) {
            const int q = nt * 8 + tg * 2 + b;
            const int pos = (q & 32) + ((q & 3) << 3) + ((q >> 2) & 7);
            qkp[r0 * 72 + pos] = f2tf(c[nt][b]     * inv0);
            qkp[r1 * 72 + pos] = f2tf(c[nt][2 + b] * inv1);
        }
    __syncthreads();

    uint32_t ap[2][2][8];
#pragma unroll
    for (int h2 = 0; h2 < 2; h2++)
#pragma unroll
        for (int ch = 0; ch < 2; ch++) {
            const uint32_t* p = qkp + (w * 16 + h2 * 8 + g) * 72 + ch * 32 + tg * 8;
            *(uint4*)&ap[h2][ch][0] = *(const uint4*)p;
            *(uint4*)&ap[h2][ch][4] = *(const uint4*)(p + 4);
        }
    float o[4][4];
#pragma unroll
    for (int nt = 0; nt < 4; nt++)
#pragma unroll
        for (int i = 0; i < 4; i++) o[nt][i] = 0.f;

#pragma unroll
    for (int nt = 0; nt < 4; nt++) {
        uint32_t bf0[8], bf1[8];
        const uint32_t* p = vsm + (nt * 8 + g) * 68 + tg * 8;
        *(uint4*)&bf0[0] = *(const uint4*)p;
        *(uint4*)&bf0[4] = *(const uint4*)(p + 4);
        *(uint4*)&bf1[0] = *(const uint4*)(p + 32);
        *(uint4*)&bf1[4] = *(const uint4*)(p + 36);
#pragma unroll
        for (int j = 0; j < 4; j++)
            mma_tf32(o[nt], ap[0][0][2*j], ap[1][0][2*j], ap[0][0][2*j+1], ap[1][0][2*j+1],
                     bf0[2*j], bf0[2*j+1]);
#pragma unroll
        for (int j = 0; j < 4; j++)
            mma_tf32(o[nt], ap[0][1][2*j], ap[1][1][2*j], ap[0][1][2*j+1], ap[1][1][2*j+1],
                     bf1[2*j], bf1[2*j+1]);
    }

    float* ob = g_ao + (size_t)win * 16384 + hh * 32;
#pragma unroll
    for (int nt = 0; nt < 4; nt++) {
        const int d = nt * 8 + tg * 2;
        *(float2*)&ob[(size_t)r0 * 256 + d] = make_float2(o[nt][0], o[nt][1]);
        *(float2*)&ob[(size_t)r1 * 256 + d] = make_float2(o[nt][2], o[nt][3]);
    }
}

// ---------------------------------------------------------------------------
extern "C" void kernel_launch(void* const* d_in, const int* in_sizes, int n_in,
                              void* d_out, int out_size)
{
    const float* x       = (const float*)d_in[0];
    const float* w_qkv   = (const float*)d_in[1];
    const float* b_qkv   = (const float*)d_in[2];
    const float* rel_pos = (const float*)d_in[3];
    const float* w_out   = (const float*)d_in[4];
    const float* b_out   = (const float*)d_in[5];
    float* out = (float*)d_out;

    cudaFuncSetAttribute((const void*)gemm_tf32<0>,
                         cudaFuncAttributeMaxDynamicSharedMemorySize, GEMM_SMEM);
    cudaFuncSetAttribute((const void*)gemm_tf32<1>,
                         cudaFuncAttributeMaxDynamicSharedMemorySize, GEMM_SMEM);

    gemm_tf32<0><<<4096, 256, GEMM_SMEM>>>(x, w_qkv, b_qkv, nullptr);
    attn_kernel<<<dim3(4096, 8), 128>>>(rel_pos);
    gemm_tf32<1><<<4096, 256, GEMM_SMEM>>>(nullptr, w_out, b_out, out);
}

// round 7
// speedup vs baseline: 1.0978x; 1.0315x over previous
#include <cuda_runtime.h>
#include <cstdint>

#define SCALE_Q 0.17677669529663687f   // 32^-0.5

// scratch (static device globals; no runtime allocation)
__device__ float    g_qkv[262144UL * 768]; // [m][768]: q | k | v
__device__ float    g_ao [262144UL * 256]; // [m][256]: attention output
__device__ uint32_t g_wq [768 * 256];      // packed tf32 w_qkv
__device__ uint32_t g_wo [256 * 256];      // packed tf32 w_out

__device__ __forceinline__ uint32_t f2tf(float x) {
    uint32_t r;
    asm("cvt.rna.tf32.f32 %0, %1;" : "=r"(r) : "f"(x));
    return r;
}

__device__ __forceinline__ void mma_tf32(float c[4], uint32_t a0, uint32_t a1,
                                         uint32_t a2, uint32_t a3,
                                         uint32_t b0, uint32_t b1) {
    asm volatile(
        "mma.sync.aligned.m16n8k8.row.col.f32.tf32.tf32.f32 "
        "{%0,%1,%2,%3},{%4,%5,%6,%7},{%8,%9},{%0,%1,%2,%3};\n"
        : "+f"(c[0]), "+f"(c[1]), "+f"(c[2]), "+f"(c[3])
        : "r"(a0), "r"(a1), "r"(a2), "r"(a3), "r"(b0), "r"(b1));
}

// ---------------------------------------------------------------------------
// One-time weight pack: tf32-convert + within-32-chunk fragment permute
// pos = (k & ~31) + (k&3)*8 + ((k>>2)&7)  (matches fragment layout below)
// ---------------------------------------------------------------------------
__global__ void pack_w(const float* __restrict__ wq, const float* __restrict__ wo)
{
    const int idx = blockIdx.x * 256 + threadIdx.x;   // 1024 rows x 256 k
    const int row = idx >> 8, k = idx & 255;
    const int pos = (k & ~31) + ((k & 3) << 3) + ((k >> 2) & 7);
    if (row < 768) g_wq[row * 256 + pos] = f2tf(wq[row * 256 + k]);
    else           g_wo[(row - 768) * 256 + pos] = f2tf(wo[(row - 768) * 256 + k]);
}

#define AS_STRIDE 260                   // % 32 == 4 -> conflict-free LDS.128
#define GEMM_SMEM (64 * AS_STRIDE * 4)  // ~66.6 KB -> 2 CTAs/SM

// ---------------------------------------------------------------------------
// tf32 GEMM: block 64(M), N looped in chunks of 128. A-tile in smem (packed),
// B fragments loaded DIRECTLY from pre-packed W via LDG.128 (no B smem, no
// per-iter barrier). 256 threads = 8 warps (2m x 4n), warp tile 32x32.
// ---------------------------------------------------------------------------
template <int MODE>
__global__ __launch_bounds__(256, 2) void gemm_tf32(
    const float* __restrict__ A,
    const uint32_t* __restrict__ Wp,  // packed [N][256]
    const float* __restrict__ bias,
    float* __restrict__ Cout)
{
    constexpr int NCH = (MODE == 0) ? 6 : 2;     // chunks of 128 N

    extern __shared__ uint32_t sh[];
    uint32_t* As = sh;                           // 64 x AS_STRIDE
    __shared__ const float* arow[64];
    __shared__ float*       crow[64];

    const int tid = threadIdx.x;
    const int m0  = blockIdx.x * 64;

    if (tid < 64) {
        const int m = m0 + tid;
        if (MODE == 0) {
            const int b  = m >> 16;
            const int wi = (m >> 6) & 1023;
            const int p  = m & 63;
            const int wh = wi >> 5, wc = wi & 31;
            const int pi = p >> 3,  pj = p & 7;
            const int h  = ((wh << 3) + pi + 4) & 255;   // roll(-4)
            const int w  = ((wc << 3) + pj + 4) & 255;
            arow[tid] = A + (size_t)((b << 16) | (h << 8) | w) * 256;
            crow[tid] = g_qkv + (size_t)m * 768;
        } else {
            const int bp = m >> 16;
            const int h  = (m >> 8) & 255;
            const int w  = m & 255;
            const int wh  = h >> 3, pi = h & 7;
            const int wcq = w >> 3, pj = w & 7;
            const int n   = (bp << 8) | (wh << 3) | (wcq >> 2);  // unscramble
            const int bb  = wcq & 3;
            const int p   = (pi << 3) | pj;
            arow[tid] = g_ao + ((size_t)((bb << 16) | (n << 6) | p)) * 256;
            const int fh = (h + 4) & 255, fw = (w + 4) & 255;    // roll(+4)
            crow[tid] = Cout + (size_t)((bp << 16) | (fh << 8) | fw) * 256;
        }
    }
    __syncthreads();

    // ---- A tile (64 x 256) -> smem, packed, loaded ONCE ----
#pragma unroll
    for (int i = 0; i < 16; i++) {
        const int idx = tid + i * 256;
        const int r = idx >> 6, k4 = (idx & 63) << 2;
        const float4 v = *(const float4*)(arow[r] + k4);
        uint32_t* d = As + r * AS_STRIDE + (k4 & ~31) + ((k4 >> 2) & 7);
        d[0]  = f2tf(v.x); d[8]  = f2tf(v.y);
        d[16] = f2tf(v.z); d[24] = f2tf(v.w);
    }
    __syncthreads();

    const int warp = tid >> 5, lane = tid & 31;
    const int wm = warp >> 2, wn = warp & 3;     // 2m x 4n
    const int g = lane >> 2, tg = lane & 3;

    for (int nc = 0; nc < NCH; nc++) {
        float c[2][4][4];
#pragma unroll
        for (int mt = 0; mt < 2; mt++)
#pragma unroll
            for (int nt = 0; nt < 4; nt++)
#pragma unroll
                for (int i = 0; i < 4; i++) c[mt][nt][i] = 0.f;

        const uint32_t* wbase = Wp + (size_t)(nc * 128 + wn * 32 + g) * 256 + tg * 8;

#pragma unroll 2
        for (int kc = 0; kc < 8; kc++) {
            // B fragments straight from packed W (global; L1/L2-resident)
            uint32_t bv[4][8];
#pragma unroll
            for (int nt = 0; nt < 4; nt++) {
                const uint32_t* p = wbase + (size_t)nt * 8 * 256 + kc * 32;
                *(uint4*)&bv[nt][0] = *(const uint4*)p;
                *(uint4*)&bv[nt][4] = *(const uint4*)(p + 4);
            }
            // A fragments from smem
            uint32_t av[2][2][8];
            const uint32_t* abase = As + kc * 32 + tg * 8;
#pragma unroll
            for (int mt = 0; mt < 2; mt++)
#pragma unroll
                for (int h2 = 0; h2 < 2; h2++) {
                    const uint32_t* p = abase + (wm * 32 + mt * 16 + h2 * 8 + g) * AS_STRIDE;
                    *(uint4*)&av[mt][h2][0] = *(const uint4*)p;
                    *(uint4*)&av[mt][h2][4] = *(const uint4*)(p + 4);
                }
#pragma unroll
            for (int nt = 0; nt < 4; nt++)
#pragma unroll
                for (int j = 0; j < 4; j++)
#pragma unroll
                    for (int mt = 0; mt < 2; mt++)
                        mma_tf32(c[mt][nt],
                                 av[mt][0][2*j], av[mt][1][2*j],
                                 av[mt][0][2*j+1], av[mt][1][2*j+1],
                                 bv[nt][2*j], bv[nt][2*j+1]);
        }

        // epilogue for this 128-wide N chunk
#pragma unroll
        for (int mt = 0; mt < 2; mt++)
#pragma unroll
            for (int nt = 0; nt < 4; nt++) {
                const int col = nc * 128 + wn * 32 + nt * 8 + tg * 2;
                const float b0 = bias[col], b1 = bias[col + 1];
#pragma unroll
                for (int h2 = 0; h2 < 2; h2++) {
                    const int r = wm * 32 + mt * 16 + h2 * 8 + g;
                    float v0 = c[mt][nt][h2 * 2]     + b0;
                    float v1 = c[mt][nt][h2 * 2 + 1] + b1;
                    if (MODE == 0 && col < 256) { v0 *= SCALE_Q; v1 *= SCALE_Q; }
                    crow[r][col]     = v0;
                    crow[r][col + 1] = v1;
                }
            }
    }
}

// ---------------------------------------------------------------------------
// Tensor-core attention (unchanged).
// ---------------------------------------------------------------------------
__global__ __launch_bounds__(128) void attn_kernel(const float* __restrict__ rel_pos)
{
    __shared__ uint32_t qkp[4608];   // Q[64][36] @0, K[64][36] @2304 ; P[64][72] alias
    __shared__ uint32_t vsm[32 * 68];// V^T packed [dim 32][tok 64 packed]
    __shared__ float relb[228];

    const int tid = threadIdx.x;
    const int win = blockIdx.x;
    const int hh  = blockIdx.y;
    const int wloc = win & 1023;
    const bool maskH = ((wloc >> 5) == 31);
    const bool maskW = ((wloc & 31) == 31);

    const float* base = g_qkv + (size_t)win * 49152 + hh * 32;
#pragma unroll
    for (int i = 0; i < 4; i++) {
        const int idx = tid + i * 128;
        const int t = idx >> 3, j8 = idx & 7;
        const float* src = base + (size_t)t * 768 + j8 * 4;
        const float4 q4 = *(const float4*)(src);
        const float4 k4 = *(const float4*)(src + 256);
        const float4 v4 = *(const float4*)(src + 512);
        uint32_t* qd = qkp + t * 36 + j8;
        qd[0] = f2tf(q4.x); qd[8] = f2tf(q4.y); qd[16] = f2tf(q4.z); qd[24] = f2tf(q4.w);
        uint32_t* kd = qkp + 2304 + t * 36 + j8;
        kd[0] = f2tf(k4.x); kd[8] = f2tf(k4.y); kd[16] = f2tf(k4.z); kd[24] = f2tf(k4.w);
        const int tp = (t & 32) + ((t & 3) << 3) + ((t >> 2) & 7);
        uint32_t* vd = vsm + (size_t)(j8 * 4) * 68 + tp;
        vd[0] = f2tf(v4.x); vd[68] = f2tf(v4.y); vd[136] = f2tf(v4.z); vd[204] = f2tf(v4.w);
    }
    for (int i = tid; i < 225; i += 128) relb[i] = rel_pos[hh * 225 + i];
    __syncthreads();

    const int w = tid >> 5, lane = tid & 31;
    const int g = lane >> 2, tg = lane & 3;

    uint32_t af[2][8];
#pragma unroll
    for (int h2 = 0; h2 < 2; h2++) {
        const uint32_t* p = qkp + (w * 16 + h2 * 8 + g) * 36 + tg * 8;
        *(uint4*)&af[h2][0] = *(const uint4*)p;
        *(uint4*)&af[h2][4] = *(const uint4*)(p + 4);
    }
    float c[8][4];
#pragma unroll
    for (int nt = 0; nt < 8; nt++)
#pragma unroll
        for (int i = 0; i < 4; i++) c[nt][i] = 0.f;

#pragma unroll
    for (int nt = 0; nt < 8; nt++) {
        uint32_t bf[8];
        const uint32_t* p = qkp + 2304 + (nt * 8 + g) * 36 + tg * 8;
        *(uint4*)&bf[0] = *(const uint4*)p;
        *(uint4*)&bf[4] = *(const uint4*)(p + 4);
#pragma unroll
        for (int j = 0; j < 4; j++)
            mma_tf32(c[nt], af[0][2*j], af[1][2*j], af[0][2*j+1], af[1][2*j+1],
                     bf[2*j], bf[2*j+1]);
    }

    const int r0 = w * 16 + g, r1 = r0 + 8;
    const int pi0 = r0 >> 3, pj0 = r0 & 7;
    const int pi1 = r1 >> 3, pj1 = r1 & 7;
#pragma unroll
    for (int nt = 0; nt < 8; nt++) {
#pragma unroll
        for (int b = 0; b < 2; b++) {
            const int q = nt * 8 + tg * 2 + b;
            const int qi = q >> 3, qj = q & 7;
            const bool m0 = (maskH && ((pi0 < 4) != (qi < 4))) ||
                            (maskW && ((pj0 < 4) != (qj < 4)));
            const bool m1 = (maskH && ((pi1 < 4) != (qi < 4))) ||
                            (maskW && ((pj1 < 4) != (qj < 4)));
            c[nt][b]     = m0 ? -1e30f : c[nt][b]     + relb[(pi0 - qi + 7) * 15 + (pj0 - qj + 7)];
            c[nt][2 + b] = m1 ? -1e30f : c[nt][2 + b] + relb[(pi1 - qi + 7) * 15 + (pj1 - qj + 7)];
        }
    }

    float m0 = -1e30f, m1 = -1e30f;
#pragma unroll
    for (int nt = 0; nt < 8; nt++) {
        m0 = fmaxf(m0, fmaxf(c[nt][0], c[nt][1]));
        m1 = fmaxf(m1, fmaxf(c[nt][2], c[nt][3]));
    }
    m0 = fmaxf(m0, __shfl_xor_sync(0xffffffffu, m0, 1));
    m0 = fmaxf(m0, __shfl_xor_sync(0xffffffffu, m0, 2));
    m1 = fmaxf(m1, __shfl_xor_sync(0xffffffffu, m1, 1));
    m1 = fmaxf(m1, __shfl_xor_sync(0xffffffffu, m1, 2));
    float s0 = 0.f, s1 = 0.f;
#pragma unroll
    for (int nt = 0; nt < 8; nt++) {
        c[nt][0] = __expf(c[nt][0] - m0); s0 += c[nt][0];
        c[nt][1] = __expf(c[nt][1] - m0); s0 += c[nt][1];
        c[nt][2] = __expf(c[nt][2] - m1); s1 += c[nt][2];
        c[nt][3] = __expf(c[nt][3] - m1); s1 += c[nt][3];
    }
    s0 += __shfl_xor_sync(0xffffffffu, s0, 1);
    s0 += __shfl_xor_sync(0xffffffffu, s0, 2);
    s1 += __shfl_xor_sync(0xffffffffu, s1, 1);
    s1 += __shfl_xor_sync(0xffffffffu, s1, 2);
    const float inv0 = 1.f / s0, inv1 = 1.f / s1;

    __syncthreads();

#pragma unroll
    for (int nt = 0; nt < 8; nt++)
#pragma unroll
        for (int b = 0; b < 2; b++) {
            const int q = nt * 8 + tg * 2 + b;
            const int pos = (q & 32) + ((q & 3) << 3) + ((q >> 2) & 7);
            qkp[r0 * 72 + pos] = f2tf(c[nt][b]     * inv0);
            qkp[r1 * 72 + pos] = f2tf(c[nt][2 + b] * inv1);
        }
    __syncthreads();

    uint32_t ap[2][2][8];
#pragma unroll
    for (int h2 = 0; h2 < 2; h2++)
#pragma unroll
        for (int ch = 0; ch < 2; ch++) {
            const uint32_t* p = qkp + (w * 16 + h2 * 8 + g) * 72 + ch * 32 + tg * 8;
            *(uint4*)&ap[h2][ch][0] = *(const uint4*)p;
            *(uint4*)&ap[h2][ch][4] = *(const uint4*)(p + 4);
        }
    float o[4][4];
#pragma unroll
    for (int nt = 0; nt < 4; nt++)
#pragma unroll
        for (int i = 0; i < 4; i++) o[nt][i] = 0.f;

#pragma unroll
    for (int nt = 0; nt < 4; nt++) {
        uint32_t bf0[8], bf1[8];
        const uint32_t* p = vsm + (nt * 8 + g) * 68 + tg * 8;
        *(uint4*)&bf0[0] = *(const uint4*)p;
        *(uint4*)&bf0[4] = *(const uint4*)(p + 4);
        *(uint4*)&bf1[0] = *(const uint4*)(p + 32);
        *(uint4*)&bf1[4] = *(const uint4*)(p + 36);
#pragma unroll
        for (int j = 0; j < 4; j++)
            mma_tf32(o[nt], ap[0][0][2*j], ap[1][0][2*j], ap[0][0][2*j+1], ap[1][0][2*j+1],
                     bf0[2*j], bf0[2*j+1]);
#pragma unroll
        for (int j = 0; j < 4; j++)
            mma_tf32(o[nt], ap[0][1][2*j], ap[1][1][2*j], ap[0][1][2*j+1], ap[1][1][2*j+1],
                     bf1[2*j], bf1[2*j+1]);
    }

    float* ob = g_ao + (size_t)win * 16384 + hh * 32;
#pragma unroll
    for (int nt = 0; nt < 4; nt++) {
        const int d = nt * 8 + tg * 2;
        *(float2*)&ob[(size_t)r0 * 256 + d] = make_float2(o[nt][0], o[nt][1]);
        *(float2*)&ob[(size_t)r1 * 256 + d] = make_float2(o[nt][2], o[nt][3]);
    }
}

// ---------------------------------------------------------------------------
extern "C" void kernel_launch(void* const* d_in, const int* in_sizes, int n_in,
                              void* d_out, int out_size)
{
    const float* x       = (const float*)d_in[0];
    const float* w_qkv   = (const float*)d_in[1];
    const float* b_qkv   = (const float*)d_in[2];
    const float* rel_pos = (const float*)d_in[3];
    const float* w_out   = (const float*)d_in[4];
    const float* b_out   = (const float*)d_in[5];
    float* out = (float*)d_out;

    cudaFuncSetAttribute((const void*)gemm_tf32<0>,
                         cudaFuncAttributeMaxDynamicSharedMemorySize, GEMM_SMEM);
    cudaFuncSetAttribute((const void*)gemm_tf32<1>,
                         cudaFuncAttributeMaxDynamicSharedMemorySize, GEMM_SMEM);

    uint32_t* wq;  uint32_t* wo;
    cudaGetSymbolAddress((void**)&wq, g_wq);
    cudaGetSymbolAddress((void**)&wo, g_wo);

    pack_w<<<1024, 256>>>(w_qkv, w_out);
    gemm_tf32<0><<<4096, 256, GEMM_SMEM>>>(x, wq, b_qkv, nullptr);
    attn_kernel<<<dim3(4096, 8), 128>>>(rel_pos);
    gemm_tf32<1><<<4096, 256, GEMM_SMEM>>>(nullptr, wo, b_out, out);
}

// round 8
// speedup vs baseline: 1.1249x; 1.0247x over previous
#include <cuda_runtime.h>
#include <cstdint>

#define SCALE_Q 0.17677669529663687f   // 32^-0.5

// scratch (static device globals; no runtime allocation)
__device__ uint32_t g_qkv[262144UL * 768]; // packed tf32: q | k | v
__device__ uint32_t g_ao [262144UL * 256]; // packed tf32 attention output
__device__ uint32_t g_wq [768 * 256];      // packed tf32 w_qkv
__device__ uint32_t g_wo [256 * 256];      // packed tf32 w_out

__device__ __forceinline__ uint32_t f2tf(float x) {
    uint32_t r;
    asm("cvt.rna.tf32.f32 %0, %1;" : "=r"(r) : "f"(x));
    return r;
}

__device__ __forceinline__ void mma_tf32(float c[4], uint32_t a0, uint32_t a1,
                                         uint32_t a2, uint32_t a3,
                                         uint32_t b0, uint32_t b1) {
    asm volatile(
        "mma.sync.aligned.m16n8k8.row.col.f32.tf32.tf32.f32 "
        "{%0,%1,%2,%3},{%4,%5,%6,%7},{%8,%9},{%0,%1,%2,%3};\n"
        : "+f"(c[0]), "+f"(c[1]), "+f"(c[2]), "+f"(c[3])
        : "r"(a0), "r"(a1), "r"(a2), "r"(a3), "r"(b0), "r"(b1));
}

// ---------------------------------------------------------------------------
// One-time weight pack: tf32-convert + within-32-chunk fragment permute
// pos = (k & ~31) + (k&3)*8 + ((k>>2)&7)
// ---------------------------------------------------------------------------
__global__ void pack_w(const float* __restrict__ wq, const float* __restrict__ wo)
{
    const int idx = blockIdx.x * 256 + threadIdx.x;   // 1024 rows x 256 k
    const int row = idx >> 8, k = idx & 255;
    const int pos = (k & ~31) + ((k & 3) << 3) + ((k >> 2) & 7);
    if (row < 768) g_wq[row * 256 + pos] = f2tf(wq[row * 256 + k]);
    else           g_wo[(row - 768) * 256 + pos] = f2tf(wo[(row - 768) * 256 + k]);
}

#define AS_STRIDE 260                   // % 32 == 4 -> conflict-free LDS.128
#define GEMM_SMEM (64 * AS_STRIDE * 4)  // ~66.6 KB -> 2 CTAs/SM

// ---------------------------------------------------------------------------
// tf32 GEMM: block 64(M), N in chunks of 128, A-tile in smem (packed), B
// fragments via LDG.128 from pre-packed W. MMA order j-outer: dependency
// distance 8 between hits on the same accumulator.
// MODE 0: A = x (fp32, pack at stage); output packed tf32 -> g_qkv.
// MODE 1: A = g_ao (already packed, identity-copy stage); output fp32 d_out.
// ---------------------------------------------------------------------------
template <int MODE>
__global__ __launch_bounds__(256, 2) void gemm_tf32(
    const void* __restrict__ Ain,
    const uint32_t* __restrict__ Wp,  // packed [N][256]
    const float* __restrict__ bias,
    float* __restrict__ Cout)
{
    constexpr int NCH = (MODE == 0) ? 6 : 2;

    extern __shared__ uint32_t sh[];
    uint32_t* As = sh;                           // 64 x AS_STRIDE
    __shared__ const void* arow[64];
    __shared__ void*       crow[64];

    const int tid = threadIdx.x;
    const int m0  = blockIdx.x * 64;

    if (tid < 64) {
        const int m = m0 + tid;
        if (MODE == 0) {
            const int b  = m >> 16;
            const int wi = (m >> 6) & 1023;
            const int p  = m & 63;
            const int wh = wi >> 5, wc = wi & 31;
            const int pi = p >> 3,  pj = p & 7;
            const int h  = ((wh << 3) + pi + 4) & 255;   // roll(-4)
            const int w  = ((wc << 3) + pj + 4) & 255;
            arow[tid] = (const float*)Ain + (size_t)((b << 16) | (h << 8) | w) * 256;
            crow[tid] = g_qkv + (size_t)m * 768;
        } else {
            const int bp = m >> 16;
            const int h  = (m >> 8) & 255;
            const int w  = m & 255;
            const int wh  = h >> 3, pi = h & 7;
            const int wcq = w >> 3, pj = w & 7;
            const int n   = (bp << 8) | (wh << 3) | (wcq >> 2);  // unscramble
            const int bb  = wcq & 3;
            const int p   = (pi << 3) | pj;
            arow[tid] = g_ao + ((size_t)((bb << 16) | (n << 6) | p)) * 256;
            const int fh = (h + 4) & 255, fw = (w + 4) & 255;    // roll(+4)
            crow[tid] = Cout + (size_t)((bp << 16) | (fh << 8) | fw) * 256;
        }
    }
    __syncthreads();

    // ---- A tile (64 x 256) -> smem, loaded ONCE ----
#pragma unroll
    for (int i = 0; i < 16; i++) {
        const int idx = tid + i * 256;
        const int r = idx >> 6, k4 = (idx & 63) << 2;
        if (MODE == 0) {   // fp32 source: tf32-convert + fragment permute
            const float4 v = *(const float4*)((const float*)arow[r] + k4);
            uint32_t* d = As + r * AS_STRIDE + (k4 & ~31) + ((k4 >> 2) & 7);
            d[0]  = f2tf(v.x); d[8]  = f2tf(v.y);
            d[16] = f2tf(v.z); d[24] = f2tf(v.w);
        } else {           // already packed: identity uint4 copy
            const uint4 v = *(const uint4*)((const uint32_t*)arow[r] + k4);
            *(uint4*)(As + r * AS_STRIDE + k4) = v;
        }
    }
    __syncthreads();

    const int warp = tid >> 5, lane = tid & 31;
    const int wm = warp >> 2, wn = warp & 3;     // 2m x 4n
    const int g = lane >> 2, tg = lane & 3;

    for (int nc = 0; nc < NCH; nc++) {
        float c[2][4][4];
#pragma unroll
        for (int mt = 0; mt < 2; mt++)
#pragma unroll
            for (int nt = 0; nt < 4; nt++)
#pragma unroll
                for (int i = 0; i < 4; i++) c[mt][nt][i] = 0.f;

        const uint32_t* wbase = Wp + (size_t)(nc * 128 + wn * 32 + g) * 256 + tg * 8;

#pragma unroll 2
        for (int kc = 0; kc < 8; kc++) {
            uint32_t bv[4][8];
#pragma unroll
            for (int nt = 0; nt < 4; nt++) {
                const uint32_t* p = wbase + (size_t)nt * 8 * 256 + kc * 32;
                *(uint4*)&bv[nt][0] = *(const uint4*)p;
                *(uint4*)&bv[nt][4] = *(const uint4*)(p + 4);
            }
            uint32_t av[2][2][8];
            const uint32_t* abase = As + kc * 32 + tg * 8;
#pragma unroll
            for (int mt = 0; mt < 2; mt++)
#pragma unroll
                for (int h2 = 0; h2 < 2; h2++) {
                    const uint32_t* p = abase + (wm * 32 + mt * 16 + h2 * 8 + g) * AS_STRIDE;
                    *(uint4*)&av[mt][h2][0] = *(const uint4*)p;
                    *(uint4*)&av[mt][h2][4] = *(const uint4*)(p + 4);
                }
            // j-outer: each accumulator hit every 8 MMAs
#pragma unroll
            for (int j = 0; j < 4; j++)
#pragma unroll
                for (int nt = 0; nt < 4; nt++)
#pragma unroll
                    for (int mt = 0; mt < 2; mt++)
                        mma_tf32(c[mt][nt],
                                 av[mt][0][2*j], av[mt][1][2*j],
                                 av[mt][0][2*j+1], av[mt][1][2*j+1],
                                 bv[nt][2*j], bv[nt][2*j+1]);
        }

        // epilogue
#pragma unroll
        for (int mt = 0; mt < 2; mt++)
#pragma unroll
            for (int nt = 0; nt < 4; nt++) {
                const int col = nc * 128 + wn * 32 + nt * 8 + tg * 2;
                const float b0 = bias[col], b1 = bias[col + 1];
#pragma unroll
                for (int h2 = 0; h2 < 2; h2++) {
                    const int r = wm * 32 + mt * 16 + h2 * 8 + g;
                    float v0 = c[mt][nt][h2 * 2]     + b0;
                    float v1 = c[mt][nt][h2 * 2 + 1] + b1;
                    if (MODE == 0) {
                        if (col < 256) { v0 *= SCALE_Q; v1 *= SCALE_Q; }
                        // store packed tf32 (pos within 32-chunk; d even -> pos, pos+8)
                        const int d = col & 31;
                        const int pos = (col & ~31) + ((d & 3) << 3) + (d >> 2);
                        uint32_t* cr = (uint32_t*)crow[r];
                        cr[pos]     = f2tf(v0);
                        cr[pos + 8] = f2tf(v1);
                    } else {
                        float* cr = (float*)crow[r];
                        cr[col]     = v0;
                        cr[col + 1] = v1;
                    }
                }
            }
    }
}

// ---------------------------------------------------------------------------
// Tensor-core attention. qkv arrives packed tf32 -> loader is pure copies.
// MMA chains re-ordered for dependency distance 4.
// ---------------------------------------------------------------------------
__global__ __launch_bounds__(128) void attn_kernel(const float* __restrict__ rel_pos)
{
    __shared__ uint32_t qkp[4608];   // Q[64][36] @0, K[64][36] @2304 ; P[64][72] alias
    __shared__ uint32_t vsm[32 * 68];// V^T [dim 32][tok 64 packed]
    __shared__ float relb[228];

    const int tid = threadIdx.x;
    const int win = blockIdx.x;
    const int hh  = blockIdx.y;
    const int wloc = win & 1023;
    const bool maskH = ((wloc >> 5) == 31);
    const bool maskW = ((wloc & 31) == 31);

    // ---- load q/k/v (already tf32-packed) ----
    const uint32_t* base = g_qkv + (size_t)win * 49152 + hh * 32;
#pragma unroll
    for (int i = 0; i < 4; i++) {
        const int idx = tid + i * 128;
        const int t = idx >> 3, e = idx & 7;
        const uint32_t* src = base + (size_t)t * 768 + e * 4;
        *(uint4*)(qkp + t * 36 + e * 4)        = *(const uint4*)(src);
        *(uint4*)(qkp + 2304 + t * 36 + e * 4) = *(const uint4*)(src + 256);
        const uint4 v4 = *(const uint4*)(src + 512);
        // v components sit at packed pos = e*4+c ; dim d = (pos&7)*4 + (pos>>3)
        const int tp = (t & 32) + ((t & 3) << 3) + ((t >> 2) & 7);
#pragma unroll
        for (int cc = 0; cc < 4; cc++) {
            const int pos = e * 4 + cc;
            const int d = ((pos & 7) << 2) + (pos >> 3);
            vsm[d * 68 + tp] = (&v4.x)[cc];
        }
    }
    for (int i = tid; i < 225; i += 128) relb[i] = rel_pos[hh * 225 + i];
    __syncthreads();

    const int w = tid >> 5, lane = tid & 31;
    const int g = lane >> 2, tg = lane & 3;

    // ---- QK^T: nt in quads, j-outer (dependency distance 4) ----
    uint32_t af[2][8];
#pragma unroll
    for (int h2 = 0; h2 < 2; h2++) {
        const uint32_t* p = qkp + (w * 16 + h2 * 8 + g) * 36 + tg * 8;
        *(uint4*)&af[h2][0] = *(const uint4*)p;
        *(uint4*)&af[h2][4] = *(const uint4*)(p + 4);
    }
    float c[8][4];
#pragma unroll
    for (int nt = 0; nt < 8; nt++)
#pragma unroll
        for (int i = 0; i < 4; i++) c[nt][i] = 0.f;

#pragma unroll
    for (int ng = 0; ng < 2; ng++) {
        uint32_t bf[4][8];
#pragma unroll
        for (int q4 = 0; q4 < 4; q4++) {
            const uint32_t* p = qkp + 2304 + ((ng * 4 + q4) * 8 + g) * 36 + tg * 8;
            *(uint4*)&bf[q4][0] = *(const uint4*)p;
            *(uint4*)&bf[q4][4] = *(const uint4*)(p + 4);
        }
#pragma unroll
        for (int j = 0; j < 4; j++)
#pragma unroll
            for (int q4 = 0; q4 < 4; q4++)
                mma_tf32(c[ng * 4 + q4],
                         af[0][2*j], af[1][2*j], af[0][2*j+1], af[1][2*j+1],
                         bf[q4][2*j], bf[q4][2*j+1]);
    }

    // ---- rel-pos bias + shift mask ----
    const int r0 = w * 16 + g, r1 = r0 + 8;
    const int pi0 = r0 >> 3, pj0 = r0 & 7;
    const int pi1 = r1 >> 3, pj1 = r1 & 7;
#pragma unroll
    for (int nt = 0; nt < 8; nt++) {
#pragma unroll
        for (int b = 0; b < 2; b++) {
            const int q = nt * 8 + tg * 2 + b;
            const int qi = q >> 3, qj = q & 7;
            const bool m0 = (maskH && ((pi0 < 4) != (qi < 4))) ||
                            (maskW && ((pj0 < 4) != (qj < 4)));
            const bool m1 = (maskH && ((pi1 < 4) != (qi < 4))) ||
                            (maskW && ((pj1 < 4) != (qj < 4)));
            c[nt][b]     = m0 ? -1e30f : c[nt][b]     + relb[(pi0 - qi + 7) * 15 + (pj0 - qj + 7)];
            c[nt][2 + b] = m1 ? -1e30f : c[nt][2 + b] + relb[(pi1 - qi + 7) * 15 + (pj1 - qj + 7)];
        }
    }

    // ---- softmax in registers ----
    float m0 = -1e30f, m1 = -1e30f;
#pragma unroll
    for (int nt = 0; nt < 8; nt++) {
        m0 = fmaxf(m0, fmaxf(c[nt][0], c[nt][1]));
        m1 = fmaxf(m1, fmaxf(c[nt][2], c[nt][3]));
    }
    m0 = fmaxf(m0, __shfl_xor_sync(0xffffffffu, m0, 1));
    m0 = fmaxf(m0, __shfl_xor_sync(0xffffffffu, m0, 2));
    m1 = fmaxf(m1, __shfl_xor_sync(0xffffffffu, m1, 1));
    m1 = fmaxf(m1, __shfl_xor_sync(0xffffffffu, m1, 2));
    float s0 = 0.f, s1 = 0.f;
#pragma unroll
    for (int nt = 0; nt < 8; nt++) {
        c[nt][0] = __expf(c[nt][0] - m0); s0 += c[nt][0];
        c[nt][1] = __expf(c[nt][1] - m0); s0 += c[nt][1];
        c[nt][2] = __expf(c[nt][2] - m1); s1 += c[nt][2];
        c[nt][3] = __expf(c[nt][3] - m1); s1 += c[nt][3];
    }
    s0 += __shfl_xor_sync(0xffffffffu, s0, 1);
    s0 += __shfl_xor_sync(0xffffffffu, s0, 2);
    s1 += __shfl_xor_sync(0xffffffffu, s1, 1);
    s1 += __shfl_xor_sync(0xffffffffu, s1, 2);
    const float inv0 = 1.f / s0, inv1 = 1.f / s1;

    __syncthreads();    // Q/K smem reads done -> safe to overwrite with P

#pragma unroll
    for (int nt = 0; nt < 8; nt++)
#pragma unroll
        for (int b = 0; b < 2; b++) {
            const int q = nt * 8 + tg * 2 + b;
            const int pos = (q & 32) + ((q & 3) << 3) + ((q >> 2) & 7);
            qkp[r0 * 72 + pos] = f2tf(c[nt][b]     * inv0);
            qkp[r1 * 72 + pos] = f2tf(c[nt][2 + b] * inv1);
        }
    __syncthreads();

    // ---- PV: chunk-outer, j-outer over 4 nt (dependency distance 4) ----
    uint32_t ap[2][2][8];
#pragma unroll
    for (int h2 = 0; h2 < 2; h2++)
#pragma unroll
        for (int ch = 0; ch < 2; ch++) {
            const uint32_t* p = qkp + (w * 16 + h2 * 8 + g) * 72 + ch * 32 + tg * 8;
            *(uint4*)&ap[h2][ch][0] = *(const uint4*)p;
            *(uint4*)&ap[h2][ch][4] = *(const uint4*)(p + 4);
        }
    float o[4][4];
#pragma unroll
    for (int nt = 0; nt < 4; nt++)
#pragma unroll
        for (int i = 0; i < 4; i++) o[nt][i] = 0.f;

#pragma unroll
    for (int ch = 0; ch < 2; ch++) {
        uint32_t bf[4][8];
#pragma unroll
        for (int nt = 0; nt < 4; nt++) {
            const uint32_t* p = vsm + (nt * 8 + g) * 68 + ch * 32 + tg * 8;
            *(uint4*)&bf[nt][0] = *(const uint4*)p;
            *(uint4*)&bf[nt][4] = *(const uint4*)(p + 4);
        }
#pragma unroll
        for (int j = 0; j < 4; j++)
#pragma unroll
            for (int nt = 0; nt < 4; nt++)
                mma_tf32(o[nt],
                         ap[0][ch][2*j], ap[1][ch][2*j],
                         ap[0][ch][2*j+1], ap[1][ch][2*j+1],
                         bf[nt][2*j], bf[nt][2*j+1]);
    }

    // ---- write out packed tf32 (GEMM1 consumes directly) ----
    uint32_t* ob = g_ao + (size_t)win * 16384 + hh * 32;
#pragma unroll
    for (int nt = 0; nt < 4; nt++) {
        const int d = nt * 8 + tg * 2;               // even
        const int pos = ((d & 3) << 3) + (d >> 2);
        ob[(size_t)r0 * 256 + pos]     = f2tf(o[nt][0]);
        ob[(size_t)r0 * 256 + pos + 8] = f2tf(o[nt][1]);
        ob[(size_t)r1 * 256 + pos]     = f2tf(o[nt][2]);
        ob[(size_t)r1 * 256 + pos + 8] = f2tf(o[nt][3]);
    }
}

// ---------------------------------------------------------------------------
extern "C" void kernel_launch(void* const* d_in, const int* in_sizes, int n_in,
                              void* d_out, int out_size)
{
    const float* x       = (const float*)d_in[0];
    const float* w_qkv   = (const float*)d_in[1];
    const float* b_qkv   = (const float*)d_in[2];
    const float* rel_pos = (const float*)d_in[3];
    const float* w_out   = (const float*)d_in[4];
    const float* b_out   = (const float*)d_in[5];
    float* out = (float*)d_out;

    cudaFuncSetAttribute((const void*)gemm_tf32<0>,
                         cudaFuncAttributeMaxDynamicSharedMemorySize, GEMM_SMEM);
    cudaFuncSetAttribute((const void*)gemm_tf32<1>,
                         cudaFuncAttributeMaxDynamicSharedMemorySize, GEMM_SMEM);

    uint32_t* wq;  uint32_t* wo;
    cudaGetSymbolAddress((void**)&wq, g_wq);
    cudaGetSymbolAddress((void**)&wo, g_wo);

    pack_w<<<1024, 256>>>(w_qkv, w_out);
    gemm_tf32<0><<<4096, 256, GEMM_SMEM>>>(x, wq, b_qkv, nullptr);
    attn_kernel<<<dim3(4096, 8), 128>>>(rel_pos);
    gemm_tf32<1><<<4096, 256, GEMM_SMEM>>>(nullptr, wo, b_out, out);
}

// round 9
// speedup vs baseline: 1.2863x; 1.1435x over previous
#include <cuda_runtime.h>
#include <cstdint>

#define SCALE_Q 0.17677669529663687f   // 32^-0.5

// scratch (static device globals; no runtime allocation)
__device__ uint32_t g_qkv[262144UL * 768]; // plain tf32 bits: q | k | v
__device__ uint32_t g_ao [262144UL * 256]; // plain tf32 attention output
__device__ uint32_t g_wq [768 * 256];      // fragment-packed tf32 w_qkv
__device__ uint32_t g_wo [256 * 256];      // fragment-packed tf32 w_out

__device__ __forceinline__ uint32_t f2tf(float x) {
    uint32_t r;
    asm("cvt.rna.tf32.f32 %0, %1;" : "=r"(r) : "f"(x));
    return r;
}

__device__ __forceinline__ void mma_tf32(float c[4], uint32_t a0, uint32_t a1,
                                         uint32_t a2, uint32_t a3,
                                         uint32_t b0, uint32_t b1) {
    asm volatile(
        "mma.sync.aligned.m16n8k8.row.col.f32.tf32.tf32.f32 "
        "{%0,%1,%2,%3},{%4,%5,%6,%7},{%8,%9},{%0,%1,%2,%3};\n"
        : "+f"(c[0]), "+f"(c[1]), "+f"(c[2]), "+f"(c[3])
        : "r"(a0), "r"(a1), "r"(a2), "r"(a3), "r"(b0), "r"(b1));
}

// ldmatrix x4 on 32-bit rows: tile i (8 rows x 4 u32) addressed by lanes 8i..8i+7;
// thread gets reg i = element [row lane>>2][col32 lane&3] of tile i.
__device__ __forceinline__ void ldsm4(uint32_t& r0, uint32_t& r1,
                                      uint32_t& r2, uint32_t& r3, uint32_t addr) {
    asm volatile("ldmatrix.sync.aligned.m8n8.x4.shared.b16 {%0,%1,%2,%3}, [%4];"
                 : "=r"(r0), "=r"(r1), "=r"(r2), "=r"(r3) : "r"(addr));
}

__device__ __forceinline__ uint32_t smem_u32(const void* p) {
    return (uint32_t)__cvta_generic_to_shared(p);
}

// ---------------------------------------------------------------------------
// One-time weight pack (B operand only): tf32 + fragment permute
// pos = (k & ~31) + (k&3)*8 + ((k>>2)&7)
// ---------------------------------------------------------------------------
__global__ void pack_w(const float* __restrict__ wq, const float* __restrict__ wo)
{
    const int idx = blockIdx.x * 256 + threadIdx.x;   // 1024 rows x 256 k
    const int row = idx >> 8, k = idx & 255;
    const int pos = (k & ~31) + ((k & 3) << 3) + ((k >> 2) & 7);
    if (row < 768) g_wq[row * 256 + pos] = f2tf(wq[row * 256 + k]);
    else           g_wo[(row - 768) * 256 + pos] = f2tf(wo[(row - 768) * 256 + k]);
}

#define AS_STRIDE 260                   // % 32 == 4 -> conflict-free ldmatrix
#define GEMM_SMEM (64 * AS_STRIDE * 4)  // ~66.6 KB -> 2 CTAs/SM

// ---------------------------------------------------------------------------
// tf32 GEMM: block 64(M), N in chunks of 128. A-tile PLAIN row-major in smem
// (STS.128 stage), fragments via ldmatrix.x4. B via LDG.128 from packed W.
// 256 threads = 8 warps (2m x 4n), warp tile 32x32.
// ---------------------------------------------------------------------------
template <int MODE>
__global__ __launch_bounds__(256, 2) void gemm_tf32(
    const void* __restrict__ Ain,
    const uint32_t* __restrict__ Wp,  // packed [N][256]
    const float* __restrict__ bias,
    float* __restrict__ Cout)
{
    constexpr int NCH = (MODE == 0) ? 6 : 2;

    extern __shared__ uint32_t sh[];
    uint32_t* As = sh;                           // 64 x AS_STRIDE, plain rows
    __shared__ const void* arow[64];
    __shared__ void*       crow[64];

    const int tid = threadIdx.x;
    const int m0  = blockIdx.x * 64;

    if (tid < 64) {
        const int m = m0 + tid;
        if (MODE == 0) {
            const int b  = m >> 16;
            const int wi = (m >> 6) & 1023;
            const int p  = m & 63;
            const int wh = wi >> 5, wc = wi & 31;
            const int pi = p >> 3,  pj = p & 7;
            const int h  = ((wh << 3) + pi + 4) & 255;   // roll(-4)
            const int w  = ((wc << 3) + pj + 4) & 255;
            arow[tid] = (const float*)Ain + (size_t)((b << 16) | (h << 8) | w) * 256;
            crow[tid] = g_qkv + (size_t)m * 768;
        } else {
            const int bp = m >> 16;
            const int h  = (m >> 8) & 255;
            const int w  = m & 255;
            const int wh  = h >> 3, pi = h & 7;
            const int wcq = w >> 3, pj = w & 7;
            const int n   = (bp << 8) | (wh << 3) | (wcq >> 2);  // unscramble
            const int bb  = wcq & 3;
            const int p   = (pi << 3) | pj;
            arow[tid] = g_ao + ((size_t)((bb << 16) | (n << 6) | p)) * 256;
            const int fh = (h + 4) & 255, fw = (w + 4) & 255;    // roll(+4)
            crow[tid] = Cout + (size_t)((bp << 16) | (fh << 8) | fw) * 256;
        }
    }
    __syncthreads();

    // ---- A tile (64 x 256) -> smem PLAIN, STS.128, loaded ONCE ----
#pragma unroll
    for (int i = 0; i < 16; i++) {
        const int idx = tid + i * 256;
        const int r = idx >> 6, k4 = (idx & 63) << 2;
        if (MODE == 0) {
            const float4 v = *(const float4*)((const float*)arow[r] + k4);
            *(uint4*)(As + r * AS_STRIDE + k4) =
                make_uint4(f2tf(v.x), f2tf(v.y), f2tf(v.z), f2tf(v.w));
        } else {
            *(uint4*)(As + r * AS_STRIDE + k4) =
                *(const uint4*)((const uint32_t*)arow[r] + k4);
        }
    }
    __syncthreads();

    const int warp = tid >> 5, lane = tid & 31;
    const int wm = warp >> 2, wn = warp & 3;     // 2m x 4n
    const int g = lane >> 2, tg = lane & 3;
    const int lrow = lane & 15;
    const int lcol = (lane >> 4) << 2;           // 0 or 4
    const uint32_t as_u32 = smem_u32(As);

    for (int nc = 0; nc < NCH; nc++) {
        float c[2][4][4];
#pragma unroll
        for (int mt = 0; mt < 2; mt++)
#pragma unroll
            for (int nt = 0; nt < 4; nt++)
#pragma unroll
                for (int i = 0; i < 4; i++) c[mt][nt][i] = 0.f;

        const uint32_t* wbase = Wp + (size_t)(nc * 128 + wn * 32 + g) * 256 + tg * 8;

#pragma unroll 2
        for (int kc = 0; kc < 8; kc++) {
            uint32_t bv[4][8];
#pragma unroll
            for (int nt = 0; nt < 4; nt++) {
                const uint32_t* p = wbase + (size_t)nt * 8 * 256 + kc * 32;
                *(uint4*)&bv[nt][0] = *(const uint4*)p;
                *(uint4*)&bv[nt][4] = *(const uint4*)(p + 4);
            }
            uint32_t av[2][16];
#pragma unroll
            for (int mt = 0; mt < 2; mt++) {
                const uint32_t ra = as_u32 +
                    (((wm * 32 + mt * 16 + lrow) * AS_STRIDE) + kc * 32 + lcol) * 4;
#pragma unroll
                for (int j = 0; j < 4; j++)
                    ldsm4(av[mt][4*j], av[mt][4*j+1], av[mt][4*j+2], av[mt][4*j+3],
                          ra + j * 32);
            }
#pragma unroll
            for (int j = 0; j < 4; j++)
#pragma unroll
                for (int nt = 0; nt < 4; nt++)
#pragma unroll
                    for (int mt = 0; mt < 2; mt++)
                        mma_tf32(c[mt][nt],
                                 av[mt][4*j], av[mt][4*j+1],
                                 av[mt][4*j+2], av[mt][4*j+3],
                                 bv[nt][2*j], bv[nt][2*j+1]);
        }

        // epilogue (plain layouts)
#pragma unroll
        for (int mt = 0; mt < 2; mt++)
#pragma unroll
            for (int nt = 0; nt < 4; nt++) {
                const int col = nc * 128 + wn * 32 + nt * 8 + tg * 2;
                const float b0 = bias[col], b1 = bias[col + 1];
#pragma unroll
                for (int h2 = 0; h2 < 2; h2++) {
                    const int r = wm * 32 + mt * 16 + h2 * 8 + g;
                    float v0 = c[mt][nt][h2 * 2]     + b0;
                    float v1 = c[mt][nt][h2 * 2 + 1] + b1;
                    if (MODE == 0) {
                        if (col < 256) { v0 *= SCALE_Q; v1 *= SCALE_Q; }
                        *(uint2*)((uint32_t*)crow[r] + col) =
                            make_uint2(f2tf(v0), f2tf(v1));
                    } else {
                        *(float2*)((float*)crow[r] + col) = make_float2(v0, v1);
                    }
                }
            }
    }
}

// ---------------------------------------------------------------------------
// Tensor-core attention: plain smem layouts + ldmatrix fragments.
// ---------------------------------------------------------------------------
__global__ __launch_bounds__(128) void attn_kernel(const float* __restrict__ rel_pos)
{
    __shared__ uint32_t qkp[4608];   // Q[64][36] @0, K[64][36] @2304 ; P[64][68] alias
    __shared__ uint32_t vsm[32 * 68];// V^T [dim 32][tok 64 packed]
    __shared__ float relb[228];

    const int tid = threadIdx.x;
    const int win = blockIdx.x;
    const int hh  = blockIdx.y;
    const int wloc = win & 1023;
    const bool maskH = ((wloc >> 5) == 31);
    const bool maskW = ((wloc & 31) == 31);

    // ---- load q/k/v (plain tf32 bits) ----
    const uint32_t* base = g_qkv + (size_t)win * 49152 + hh * 32;
#pragma unroll
    for (int i = 0; i < 4; i++) {
        const int idx = tid + i * 128;
        const int t = idx >> 3, e = idx & 7;
        const uint32_t* src = base + (size_t)t * 768 + e * 4;
        *(uint4*)(qkp + t * 36 + e * 4)        = *(const uint4*)(src);
        *(uint4*)(qkp + 2304 + t * 36 + e * 4) = *(const uint4*)(src + 256);
        const uint4 v4 = *(const uint4*)(src + 512);
        const int tp = (t & 32) + ((t & 3) << 3) + ((t >> 2) & 7);  // packed tok
#pragma unroll
        for (int cc = 0; cc < 4; cc++) {
            const int d = e * 4 + cc;          // plain dim
            vsm[d * 68 + tp] = (&v4.x)[cc];
        }
    }
    for (int i = tid; i < 225; i += 128) relb[i] = rel_pos[hh * 225 + i];
    __syncthreads();

    const int w = tid >> 5, lane = tid & 31;
    const int g = lane >> 2, tg = lane & 3;
    const int lrow = lane & 15;
    const int lcol = (lane >> 4) << 2;
    const uint32_t qk_u32 = smem_u32(qkp);

    // ---- Q fragments via ldmatrix ----
    uint32_t af[16];
    {
        const uint32_t qa = qk_u32 + (((w * 16 + lrow) * 36) + lcol) * 4;
#pragma unroll
        for (int j = 0; j < 4; j++)
            ldsm4(af[4*j], af[4*j+1], af[4*j+2], af[4*j+3], qa + j * 32);
    }

    float c[8][4];
#pragma unroll
    for (int nt = 0; nt < 8; nt++)
#pragma unroll
        for (int i = 0; i < 4; i++) c[nt][i] = 0.f;

    // ---- QK^T: K fragments via ldmatrix (n-major rows = tokens) ----
    const uint32_t k_lane = ((lane & 7) * 36 + ((lane >> 3) << 2)) * 4;
#pragma unroll
    for (int ng = 0; ng < 2; ng++) {
        uint32_t bf[4][8];
#pragma unroll
        for (int q4 = 0; q4 < 4; q4++) {
            const uint32_t ka = qk_u32 + (2304 + (ng * 4 + q4) * 8 * 36) * 4 + k_lane;
            ldsm4(bf[q4][0], bf[q4][1], bf[q4][2], bf[q4][3], ka);
            ldsm4(bf[q4][4], bf[q4][5], bf[q4][6], bf[q4][7], ka + 64);
        }
#pragma unroll
        for (int j = 0; j < 4; j++)
#pragma unroll
            for (int q4 = 0; q4 < 4; q4++)
                mma_tf32(c[ng * 4 + q4],
                         af[4*j], af[4*j+1], af[4*j+2], af[4*j+3],
                         bf[q4][2*j], bf[q4][2*j+1]);
    }

    // ---- rel-pos bias + shift mask ----
    const int r0 = w * 16 + g, r1 = r0 + 8;
    const int pi0 = r0 >> 3, pj0 = r0 & 7;
    const int pi1 = r1 >> 3, pj1 = r1 & 7;
#pragma unroll
    for (int nt = 0; nt < 8; nt++) {
#pragma unroll
        for (int b = 0; b < 2; b++) {
            const int q = nt * 8 + tg * 2 + b;
            const int qi = q >> 3, qj = q & 7;
            const bool m0 = (maskH && ((pi0 < 4) != (qi < 4))) ||
                            (maskW && ((pj0 < 4) != (qj < 4)));
            const bool m1 = (maskH && ((pi1 < 4) != (qi < 4))) ||
                            (maskW && ((pj1 < 4) != (qj < 4)));
            c[nt][b]     = m0 ? -1e30f : c[nt][b]     + relb[(pi0 - qi + 7) * 15 + (pj0 - qj + 7)];
            c[nt][2 + b] = m1 ? -1e30f : c[nt][2 + b] + relb[(pi1 - qi + 7) * 15 + (pj1 - qj + 7)];
        }
    }

    // ---- softmax in registers ----
    float m0 = -1e30f, m1 = -1e30f;
#pragma unroll
    for (int nt = 0; nt < 8; nt++) {
        m0 = fmaxf(m0, fmaxf(c[nt][0], c[nt][1]));
        m1 = fmaxf(m1, fmaxf(c[nt][2], c[nt][3]));
    }
    m0 = fmaxf(m0, __shfl_xor_sync(0xffffffffu, m0, 1));
    m0 = fmaxf(m0, __shfl_xor_sync(0xffffffffu, m0, 2));
    m1 = fmaxf(m1, __shfl_xor_sync(0xffffffffu, m1, 1));
    m1 = fmaxf(m1, __shfl_xor_sync(0xffffffffu, m1, 2));
    float s0 = 0.f, s1 = 0.f;
#pragma unroll
    for (int nt = 0; nt < 8; nt++) {
        c[nt][0] = __expf(c[nt][0] - m0); s0 += c[nt][0];
        c[nt][1] = __expf(c[nt][1] - m0); s0 += c[nt][1];
        c[nt][2] = __expf(c[nt][2] - m1); s1 += c[nt][2];
        c[nt][3] = __expf(c[nt][3] - m1); s1 += c[nt][3];
    }
    s0 += __shfl_xor_sync(0xffffffffu, s0, 1);
    s0 += __shfl_xor_sync(0xffffffffu, s0, 2);
    s1 += __shfl_xor_sync(0xffffffffu, s1, 1);
    s1 += __shfl_xor_sync(0xffffffffu, s1, 2);
    const float inv0 = 1.f / s0, inv1 = 1.f / s1;

    __syncthreads();    // Q/K smem reads done -> safe to overwrite with P

    // ---- store P plain [row][tok], stride 68 (uint2 stores) ----
#pragma unroll
    for (int nt = 0; nt < 8; nt++) {
        const int q = nt * 8 + tg * 2;
        *(uint2*)(qkp + r0 * 68 + q) =
            make_uint2(f2tf(c[nt][0] * inv0), f2tf(c[nt][1] * inv0));
        *(uint2*)(qkp + r1 * 68 + q) =
            make_uint2(f2tf(c[nt][2] * inv1), f2tf(c[nt][3] * inv1));
    }
    __syncthreads();

    // ---- PV: P fragments via ldmatrix; V fragments from packed vsm ----
    uint32_t ap[2][16];
    {
        const uint32_t pa = qk_u32 + (((w * 16 + lrow) * 68) + lcol) * 4;
#pragma unroll
        for (int ch = 0; ch < 2; ch++)
#pragma unroll
            for (int j = 0; j < 4; j++)
                ldsm4(ap[ch][4*j], ap[ch][4*j+1], ap[ch][4*j+2], ap[ch][4*j+3],
                      pa + (ch * 32 + j * 8) * 4);
    }
    float o[4][4];
#pragma unroll
    for (int nt = 0; nt < 4; nt++)
#pragma unroll
        for (int i = 0; i < 4; i++) o[nt][i] = 0.f;

#pragma unroll
    for (int ch = 0; ch < 2; ch++) {
        uint32_t bf[4][8];
#pragma unroll
        for (int nt = 0; nt < 4; nt++) {
            const uint32_t* p = vsm + (nt * 8 + g) * 68 + ch * 32 + tg * 8;
            *(uint4*)&bf[nt][0] = *(const uint4*)p;
            *(uint4*)&bf[nt][4] = *(const uint4*)(p + 4);
        }
#pragma unroll
        for (int j = 0; j < 4; j++)
#pragma unroll
            for (int nt = 0; nt < 4; nt++)
                mma_tf32(o[nt],
                         ap[ch][4*j], ap[ch][4*j+1], ap[ch][4*j+2], ap[ch][4*j+3],
                         bf[nt][2*j], bf[nt][2*j+1]);
    }

    // ---- write out plain tf32 (GEMM1 consumes directly) ----
    uint32_t* ob = g_ao + (size_t)win * 16384 + hh * 32;
#pragma unroll
    for (int nt = 0; nt < 4; nt++) {
        const int d = nt * 8 + tg * 2;
        *(uint2*)(ob + (size_t)r0 * 256 + d) = make_uint2(f2tf(o[nt][0]), f2tf(o[nt][1]));
        *(uint2*)(ob + (size_t)r1 * 256 + d) = make_uint2(f2tf(o[nt][2]), f2tf(o[nt][3]));
    }
}

// ---------------------------------------------------------------------------
extern "C" void kernel_launch(void* const* d_in, const int* in_sizes, int n_in,
                              void* d_out, int out_size)
{
    const float* x       = (const float*)d_in[0];
    const float* w_qkv   = (const float*)d_in[1];
    const float* b_qkv   = (const float*)d_in[2];
    const float* rel_pos = (const float*)d_in[3];
    const float* w_out   = (const float*)d_in[4];
    const float* b_out   = (const float*)d_in[5];
    float* out = (float*)d_out;

    cudaFuncSetAttribute((const void*)gemm_tf32<0>,
                         cudaFuncAttributeMaxDynamicSharedMemorySize, GEMM_SMEM);
    cudaFuncSetAttribute((const void*)gemm_tf32<1>,
                         cudaFuncAttributeMaxDynamicSharedMemorySize, GEMM_SMEM);

    uint32_t* wq;  uint32_t* wo;
    cudaGetSymbolAddress((void**)&wq, g_wq);
    cudaGetSymbolAddress((void**)&wo, g_wo);

    pack_w<<<1024, 256>>>(w_qkv, w_out);
    gemm_tf32<0><<<4096, 256, GEMM_SMEM>>>(x, wq, b_qkv, nullptr);
    attn_kernel<<<dim3(4096, 8), 128>>>(rel_pos);
    gemm_tf32<1><<<4096, 256, GEMM_SMEM>>>(nullptr, wo, b_out, out);
}

// round 10
// speedup vs baseline: 1.3218x; 1.0276x over previous
#include <cuda_runtime.h>
#include <cstdint>

#define SCALE_Q 0.17677669529663687f   // 32^-0.5

// scratch (static device globals; no runtime allocation)
__device__ uint32_t g_qkv[262144UL * 768]; // plain tf32 bits: q | k | v
__device__ uint32_t g_ao [262144UL * 256]; // plain tf32 attention output
__device__ uint32_t g_wq [768 * 256];      // fragment-packed tf32 w_qkv
__device__ uint32_t g_wo [256 * 256];      // fragment-packed tf32 w_out

__device__ __forceinline__ uint32_t f2tf(float x) {
    uint32_t r;
    asm("cvt.rna.tf32.f32 %0, %1;" : "=r"(r) : "f"(x));
    return r;
}

__device__ __forceinline__ void mma_tf32(float c[4], uint32_t a0, uint32_t a1,
                                         uint32_t a2, uint32_t a3,
                                         uint32_t b0, uint32_t b1) {
    asm volatile(
        "mma.sync.aligned.m16n8k8.row.col.f32.tf32.tf32.f32 "
        "{%0,%1,%2,%3},{%4,%5,%6,%7},{%8,%9},{%0,%1,%2,%3};\n"
        : "+f"(c[0]), "+f"(c[1]), "+f"(c[2]), "+f"(c[3])
        : "r"(a0), "r"(a1), "r"(a2), "r"(a3), "r"(b0), "r"(b1));
}

__device__ __forceinline__ void ldsm4(uint32_t& r0, uint32_t& r1,
                                      uint32_t& r2, uint32_t& r3, uint32_t addr) {
    asm volatile("ldmatrix.sync.aligned.m8n8.x4.shared.b16 {%0,%1,%2,%3}, [%4];"
                 : "=r"(r0), "=r"(r1), "=r"(r2), "=r"(r3) : "r"(addr));
}

__device__ __forceinline__ uint32_t smem_u32(const void* p) {
    return (uint32_t)__cvta_generic_to_shared(p);
}

__device__ __forceinline__ void cp16(uint32_t saddr, const void* g) {
    asm volatile("cp.async.cg.shared.global [%0], [%1], 16;\n" :: "r"(saddr), "l"(g));
}

// ---------------------------------------------------------------------------
// One-time weight pack (B operand): tf32 + fragment permute
// pos = (k & ~31) + (k&3)*8 + ((k>>2)&7)
// ---------------------------------------------------------------------------
__global__ void pack_w(const float* __restrict__ wq, const float* __restrict__ wo)
{
    const int idx = blockIdx.x * 256 + threadIdx.x;   // 1024 rows x 256 k
    const int row = idx >> 8, k = idx & 255;
    const int pos = (k & ~31) + ((k & 3) << 3) + ((k >> 2) & 7);
    if (row < 768) g_wq[row * 256 + pos] = f2tf(wq[row * 256 + k]);
    else           g_wo[(row - 768) * 256 + pos] = f2tf(wo[(row - 768) * 256 + k]);
}

#define AS_STRIDE 260                   // % 32 == 4 -> conflict-free ldmatrix
#define BS_STRIDE 36                    // % 32 == 4 -> conflict-free LDS.128
#define BS_SIZE   (128 * BS_STRIDE)     // one stage: 128 rows x 32 u32
#define GEMM_SMEM ((64 * AS_STRIDE + 2 * BS_SIZE) * 4)   // ~103.5 KB -> 2 CTAs/SM

// ---------------------------------------------------------------------------
// tf32 GEMM: block 64(M), N in chunks of 128. A plain in smem (ldmatrix),
// B staged one kc ahead via cp.async double buffer (hides L2 latency).
// 256 threads = 8 warps (2m x 4n), warp tile 32x32.
// ---------------------------------------------------------------------------
template <int MODE>
__global__ __launch_bounds__(256, 2) void gemm_tf32(
    const void* __restrict__ Ain,
    const uint32_t* __restrict__ Wp,  // packed [N][256]
    const float* __restrict__ bias,
    float* __restrict__ Cout)
{
    constexpr int NCH = (MODE == 0) ? 6 : 2;
    constexpr int T   = NCH * 8;

    extern __shared__ uint32_t sh[];
    uint32_t* As = sh;                           // 64 x AS_STRIDE, plain rows
    uint32_t* Bs = sh + 64 * AS_STRIDE;          // 2 x BS_SIZE
    __shared__ const void* arow[64];
    __shared__ void*       crow[64];

    const int tid = threadIdx.x;
    const int m0  = blockIdx.x * 64;

    if (tid < 64) {
        const int m = m0 + tid;
        if (MODE == 0) {
            const int b  = m >> 16;
            const int wi = (m >> 6) & 1023;
            const int p  = m & 63;
            const int wh = wi >> 5, wc = wi & 31;
            const int pi = p >> 3,  pj = p & 7;
            const int h  = ((wh << 3) + pi + 4) & 255;   // roll(-4)
            const int w  = ((wc << 3) + pj + 4) & 255;
            arow[tid] = (const float*)Ain + (size_t)((b << 16) | (h << 8) | w) * 256;
            crow[tid] = g_qkv + (size_t)m * 768;
        } else {
            const int bp = m >> 16;
            const int h  = (m >> 8) & 255;
            const int w  = m & 255;
            const int wh  = h >> 3, pi = h & 7;
            const int wcq = w >> 3, pj = w & 7;
            const int n   = (bp << 8) | (wh << 3) | (wcq >> 2);  // unscramble
            const int bb  = wcq & 3;
            const int p   = (pi << 3) | pj;
            arow[tid] = g_ao + ((size_t)((bb << 16) | (n << 6) | p)) * 256;
            const int fh = (h + 4) & 255, fw = (w + 4) & 255;    // roll(+4)
            crow[tid] = Cout + (size_t)((bp << 16) | (fh << 8) | fw) * 256;
        }
    }
    __syncthreads();

    const uint32_t bs_u32 = smem_u32(Bs);
    const int srow = tid >> 3, sseg = tid & 7;   // staging: 2 rows per thread/iter

    // stage(it): copy B chunk [nc*128 .. +128) x [kc*32 .. +32) into buf it&1
    auto stage = [&](int it) {
        const int nc = it >> 3, kc = it & 7;
        const uint32_t sb = bs_u32 + ((it & 1) * BS_SIZE) * 4;
        const uint32_t* gp = Wp + (size_t)(nc * 128) * 256 + kc * 32;
#pragma unroll
        for (int i = 0; i < 4; i++) {
            const int row = srow + i * 32;
            cp16(sb + (row * BS_STRIDE + sseg * 4) * 4,
                 gp + (size_t)row * 256 + sseg * 4);
        }
        asm volatile("cp.async.commit_group;\n");
    };

    stage(0);

    // ---- A tile (64 x 256) -> smem PLAIN, overlapped with first B stage ----
#pragma unroll
    for (int i = 0; i < 16; i++) {
        const int idx = tid + i * 256;
        const int r = idx >> 6, k4 = (idx & 63) << 2;
        if (MODE == 0) {
            const float4 v = *(const float4*)((const float*)arow[r] + k4);
            *(uint4*)(As + r * AS_STRIDE + k4) =
                make_uint4(f2tf(v.x), f2tf(v.y), f2tf(v.z), f2tf(v.w));
        } else {
            *(uint4*)(As + r * AS_STRIDE + k4) =
                *(const uint4*)((const uint32_t*)arow[r] + k4);
        }
    }

    const int warp = tid >> 5, lane = tid & 31;
    const int wm = warp >> 2, wn = warp & 3;     // 2m x 4n
    const int g = lane >> 2, tg = lane & 3;
    const int lrow = lane & 15;
    const int lcol = (lane >> 4) << 2;
    const uint32_t as_u32 = smem_u32(As);

    float c[2][4][4];

    for (int it = 0; it < T; it++) {
        const int kc = it & 7;
        if (kc == 0) {
#pragma unroll
            for (int mt = 0; mt < 2; mt++)
#pragma unroll
                for (int nt = 0; nt < 4; nt++)
#pragma unroll
                    for (int i = 0; i < 4; i++) c[mt][nt][i] = 0.f;
        }
        if (it + 1 < T) {
            stage(it + 1);
            asm volatile("cp.async.wait_group 1;\n");
        } else {
            asm volatile("cp.async.wait_group 0;\n");
        }
        __syncthreads();    // buf it&1 ready (and A tile on it==0)

        // A fragments via ldmatrix
        uint32_t av[2][16];
#pragma unroll
        for (int mt = 0; mt < 2; mt++) {
            const uint32_t ra = as_u32 +
                (((wm * 32 + mt * 16 + lrow) * AS_STRIDE) + kc * 32 + lcol) * 4;
#pragma unroll
            for (int j = 0; j < 4; j++)
                ldsm4(av[mt][4*j], av[mt][4*j+1], av[mt][4*j+2], av[mt][4*j+3],
                      ra + j * 32);
        }
        // B fragments from staged smem
        uint32_t bv[4][8];
        const uint32_t* bsb = Bs + (it & 1) * BS_SIZE + tg * 8;
#pragma unroll
        for (int nt = 0; nt < 4; nt++) {
            const uint32_t* p = bsb + (wn * 32 + nt * 8 + g) * BS_STRIDE;
            *(uint4*)&bv[nt][0] = *(const uint4*)p;
            *(uint4*)&bv[nt][4] = *(const uint4*)(p + 4);
        }
#pragma unroll
        for (int j = 0; j < 4; j++)
#pragma unroll
            for (int nt = 0; nt < 4; nt++)
#pragma unroll
                for (int mt = 0; mt < 2; mt++)
                    mma_tf32(c[mt][nt],
                             av[mt][4*j], av[mt][4*j+1],
                             av[mt][4*j+2], av[mt][4*j+3],
                             bv[nt][2*j], bv[nt][2*j+1]);
        __syncthreads();    // all reads of buf it&1 done before restaging it

        if (kc == 7) {      // epilogue for this N chunk
            const int nc = it >> 3;
#pragma unroll
            for (int mt = 0; mt < 2; mt++)
#pragma unroll
                for (int nt = 0; nt < 4; nt++) {
                    const int col = nc * 128 + wn * 32 + nt * 8 + tg * 2;
                    const float b0 = bias[col], b1 = bias[col + 1];
#pragma unroll
                    for (int h2 = 0; h2 < 2; h2++) {
                        const int r = wm * 32 + mt * 16 + h2 * 8 + g;
                        float v0 = c[mt][nt][h2 * 2]     + b0;
                        float v1 = c[mt][nt][h2 * 2 + 1] + b1;
                        if (MODE == 0) {
                            if (col < 256) { v0 *= SCALE_Q; v1 *= SCALE_Q; }
                            *(uint2*)((uint32_t*)crow[r] + col) =
                                make_uint2(f2tf(v0), f2tf(v1));
                        } else {
                            *(float2*)((float*)crow[r] + col) = make_float2(v0, v1);
                        }
                    }
                }
        }
    }
}

// ---------------------------------------------------------------------------
// Tensor-core attention (unchanged from round 9).
// ---------------------------------------------------------------------------
__global__ __launch_bounds__(128) void attn_kernel(const float* __restrict__ rel_pos)
{
    __shared__ uint32_t qkp[4608];   // Q[64][36] @0, K[64][36] @2304 ; P[64][68] alias
    __shared__ uint32_t vsm[32 * 68];// V^T [dim 32][tok 64 packed]
    __shared__ float relb[228];

    const int tid = threadIdx.x;
    const int win = blockIdx.x;
    const int hh  = blockIdx.y;
    const int wloc = win & 1023;
    const bool maskH = ((wloc >> 5) == 31);
    const bool maskW = ((wloc & 31) == 31);

    const uint32_t* base = g_qkv + (size_t)win * 49152 + hh * 32;
#pragma unroll
    for (int i = 0; i < 4; i++) {
        const int idx = tid + i * 128;
        const int t = idx >> 3, e = idx & 7;
        const uint32_t* src = base + (size_t)t * 768 + e * 4;
        *(uint4*)(qkp + t * 36 + e * 4)        = *(const uint4*)(src);
        *(uint4*)(qkp + 2304 + t * 36 + e * 4) = *(const uint4*)(src + 256);
        const uint4 v4 = *(const uint4*)(src + 512);
        const int tp = (t & 32) + ((t & 3) << 3) + ((t >> 2) & 7);
#pragma unroll
        for (int cc = 0; cc < 4; cc++) {
            const int d = e * 4 + cc;
            vsm[d * 68 + tp] = (&v4.x)[cc];
        }
    }
    for (int i = tid; i < 225; i += 128) relb[i] = rel_pos[hh * 225 + i];
    __syncthreads();

    const int w = tid >> 5, lane = tid & 31;
    const int g = lane >> 2, tg = lane & 3;
    const int lrow = lane & 15;
    const int lcol = (lane >> 4) << 2;
    const uint32_t qk_u32 = smem_u32(qkp);

    uint32_t af[16];
    {
        const uint32_t qa = qk_u32 + (((w * 16 + lrow) * 36) + lcol) * 4;
#pragma unroll
        for (int j = 0; j < 4; j++)
            ldsm4(af[4*j], af[4*j+1], af[4*j+2], af[4*j+3], qa + j * 32);
    }

    float c[8][4];
#pragma unroll
    for (int nt = 0; nt < 8; nt++)
#pragma unroll
        for (int i = 0; i < 4; i++) c[nt][i] = 0.f;

    const uint32_t k_lane = ((lane & 7) * 36 + ((lane >> 3) << 2)) * 4;
#pragma unroll
    for (int ng = 0; ng < 2; ng++) {
        uint32_t bf[4][8];
#pragma unroll
        for (int q4 = 0; q4 < 4; q4++) {
            const uint32_t ka = qk_u32 + (2304 + (ng * 4 + q4) * 8 * 36) * 4 + k_lane;
            ldsm4(bf[q4][0], bf[q4][1], bf[q4][2], bf[q4][3], ka);
            ldsm4(bf[q4][4], bf[q4][5], bf[q4][6], bf[q4][7], ka + 64);
        }
#pragma unroll
        for (int j = 0; j < 4; j++)
#pragma unroll
            for (int q4 = 0; q4 < 4; q4++)
                mma_tf32(c[ng * 4 + q4],
                         af[4*j], af[4*j+1], af[4*j+2], af[4*j+3],
                         bf[q4][2*j], bf[q4][2*j+1]);
    }

    const int r0 = w * 16 + g, r1 = r0 + 8;
    const int pi0 = r0 >> 3, pj0 = r0 & 7;
    const int pi1 = r1 >> 3, pj1 = r1 & 7;
#pragma unroll
    for (int nt = 0; nt < 8; nt++) {
#pragma unroll
        for (int b = 0; b < 2; b++) {
            const int q = nt * 8 + tg * 2 + b;
            const int qi = q >> 3, qj = q & 7;
            const bool m0 = (maskH && ((pi0 < 4) != (qi < 4))) ||
                            (maskW && ((pj0 < 4) != (qj < 4)));
            const bool m1 = (maskH && ((pi1 < 4) != (qi < 4))) ||
                            (maskW && ((pj1 < 4) != (qj < 4)));
            c[nt][b]     = m0 ? -1e30f : c[nt][b]     + relb[(pi0 - qi + 7) * 15 + (pj0 - qj + 7)];
            c[nt][2 + b] = m1 ? -1e30f : c[nt][2 + b] + relb[(pi1 - qi + 7) * 15 + (pj1 - qj + 7)];
        }
    }

    float m0 = -1e30f, m1 = -1e30f;
#pragma unroll
    for (int nt = 0; nt < 8; nt++) {
        m0 = fmaxf(m0, fmaxf(c[nt][0], c[nt][1]));
        m1 = fmaxf(m1, fmaxf(c[nt][2], c[nt][3]));
    }
    m0 = fmaxf(m0, __shfl_xor_sync(0xffffffffu, m0, 1));
    m0 = fmaxf(m0, __shfl_xor_sync(0xffffffffu, m0, 2));
    m1 = fmaxf(m1, __shfl_xor_sync(0xffffffffu, m1, 1));
    m1 = fmaxf(m1, __shfl_xor_sync(0xffffffffu, m1, 2));
    float s0 = 0.f, s1 = 0.f;
#pragma unroll
    for (int nt = 0; nt < 8; nt++) {
        c[nt][0] = __expf(c[nt][0] - m0); s0 += c[nt][0];
        c[nt][1] = __expf(c[nt][1] - m0); s0 += c[nt][1];
        c[nt][2] = __expf(c[nt][2] - m1); s1 += c[nt][2];
        c[nt][3] = __expf(c[nt][3] - m1); s1 += c[nt][3];
    }
    s0 += __shfl_xor_sync(0xffffffffu, s0, 1);
    s0 += __shfl_xor_sync(0xffffffffu, s0, 2);
    s1 += __shfl_xor_sync(0xffffffffu, s1, 1);
    s1 += __shfl_xor_sync(0xffffffffu, s1, 2);
    const float inv0 = 1.f / s0, inv1 = 1.f / s1;

    __syncthreads();

#pragma unroll
    for (int nt = 0; nt < 8; nt++) {
        const int q = nt * 8 + tg * 2;
        *(uint2*)(qkp + r0 * 68 + q) =
            make_uint2(f2tf(c[nt][0] * inv0), f2tf(c[nt][1] * inv0));
        *(uint2*)(qkp + r1 * 68 + q) =
            make_uint2(f2tf(c[nt][2] * inv1), f2tf(c[nt][3] * inv1));
    }
    __syncthreads();

    uint32_t ap[2][16];
    {
        const uint32_t pa = qk_u32 + (((w * 16 + lrow) * 68) + lcol) * 4;
#pragma unroll
        for (int ch = 0; ch < 2; ch++)
#pragma unroll
            for (int j = 0; j < 4; j++)
                ldsm4(ap[ch][4*j], ap[ch][4*j+1], ap[ch][4*j+2], ap[ch][4*j+3],
                      pa + (ch * 32 + j * 8) * 4);
    }
    float o[4][4];
#pragma unroll
    for (int nt = 0; nt < 4; nt++)
#pragma unroll
        for (int i = 0; i < 4; i++) o[nt][i] = 0.f;

#pragma unroll
    for (int ch = 0; ch < 2; ch++) {
        uint32_t bf[4][8];
#pragma unroll
        for (int nt = 0; nt < 4; nt++) {
            const uint32_t* p = vsm + (nt * 8 + g) * 68 + ch * 32 + tg * 8;
            *(uint4*)&bf[nt][0] = *(const uint4*)p;
            *(uint4*)&bf[nt][4] = *(const uint4*)(p + 4);
        }
#pragma unroll
        for (int j = 0; j < 4; j++)
#pragma unroll
            for (int nt = 0; nt < 4; nt++)
                mma_tf32(o[nt],
                         ap[ch][4*j], ap[ch][4*j+1], ap[ch][4*j+2], ap[ch][4*j+3],
                         bf[nt][2*j], bf[nt][2*j+1]);
    }

    uint32_t* ob = g_ao + (size_t)win * 16384 + hh * 32;
#pragma unroll
    for (int nt = 0; nt < 4; nt++) {
        const int d = nt * 8 + tg * 2;
        *(uint2*)(ob + (size_t)r0 * 256 + d) = make_uint2(f2tf(o[nt][0]), f2tf(o[nt][1]));
        *(uint2*)(ob + (size_t)r1 * 256 + d) = make_uint2(f2tf(o[nt][2]), f2tf(o[nt][3]));
    }
}

// ---------------------------------------------------------------------------
extern "C" void kernel_launch(void* const* d_in, const int* in_sizes, int n_in,
                              void* d_out, int out_size)
{
    const float* x       = (const float*)d_in[0];
    const float* w_qkv   = (const float*)d_in[1];
    const float* b_qkv   = (const float*)d_in[2];
    const float* rel_pos = (const float*)d_in[3];
    const float* w_out   = (const float*)d_in[4];
    const float* b_out   = (const float*)d_in[5];
    float* out = (float*)d_out;

    cudaFuncSetAttribute((const void*)gemm_tf32<0>,
                         cudaFuncAttributeMaxDynamicSharedMemorySize, GEMM_SMEM);
    cudaFuncSetAttribute((const void*)gemm_tf32<1>,
                         cudaFuncAttributeMaxDynamicSharedMemorySize, GEMM_SMEM);

    uint32_t* wq;  uint32_t* wo;
    cudaGetSymbolAddress((void**)&wq, g_wq);
    cudaGetSymbolAddress((void**)&wo, g_wo);

    pack_w<<<1024, 256>>>(w_qkv, w_out);
    gemm_tf32<0><<<4096, 256, GEMM_SMEM>>>(x, wq, b_qkv, nullptr);
    attn_kernel<<<dim3(4096, 8), 128>>>(rel_pos);
    gemm_tf32<1><<<4096, 256, GEMM_SMEM>>>(nullptr, wo, b_out, out);
}